// round 13
// baseline (speedup 1.0000x reference)
#include <cuda_runtime.h>
#include <cuda_fp16.h>
#include <math.h>
#include <stdint.h>

#define S_LEN 1024
#define D_MOD 1024
#define B_SZ 4
#define N_H 16
#define MAXLEN 1024

// ---------------------------------------------------------------------------
// Scratch (device globals — no allocations allowed)
// ---------------------------------------------------------------------------
__device__ __half g_pe_hi[S_LEN * D_MOD],        g_pe_lo[S_LEN * D_MOD];
__device__ __half g_wpos_hi[2 * D_MOD * D_MOD],  g_wpos_lo[2 * D_MOD * D_MOD];
__device__ __half g_xn_hi[B_SZ * S_LEN * D_MOD], g_xn_lo[B_SZ * S_LEN * D_MOD];
__device__ __half g_wtok_hi[3 * D_MOD * D_MOD],  g_wtok_lo[3 * D_MOD * D_MOD];
__device__ __half g_ph[S_LEN * 2 * D_MOD], g_pl[S_LEN * 2 * D_MOD];                      // pos
__device__ __half g_th[(size_t)B_SZ * S_LEN * 3 * D_MOD], g_tl[(size_t)B_SZ * S_LEN * 3 * D_MOD]; // tok
__device__ float  g_P0[(size_t)N_H * S_LEN * S_LEN];      // pos_attn*SCALE + bias, 67MB

// ---------------------------------------------------------------------------
// helpers
// ---------------------------------------------------------------------------
__device__ __forceinline__ uint32_t smem_u32(const void* p) {
    uint32_t a;
    asm("{ .reg .u64 t; cvta.to.shared.u64 t, %1; cvt.u32.u64 %0, t; }" : "=r"(a) : "l"(p));
    return a;
}
__device__ __forceinline__ void cp_async16(uint32_t dst, const void* src) {
    asm volatile("cp.async.cg.shared.global [%0], [%1], 16;" :: "r"(dst), "l"(src) : "memory");
}
__device__ __forceinline__ void cp_async4(uint32_t dst, const void* src) {
    asm volatile("cp.async.ca.shared.global [%0], [%1], 4;" :: "r"(dst), "l"(src) : "memory");
}
#define CP_COMMIT() asm volatile("cp.async.commit_group;" ::: "memory")
#define CP_WAIT(n)  asm volatile("cp.async.wait_group %0;" :: "n"(n) : "memory")

__device__ __forceinline__ void ldm_x4(uint32_t* r, uint32_t addr) {
    asm volatile("ldmatrix.sync.aligned.m8n8.x4.shared.b16 {%0,%1,%2,%3}, [%4];"
                 : "=r"(r[0]), "=r"(r[1]), "=r"(r[2]), "=r"(r[3]) : "r"(addr));
}
__device__ __forceinline__ void ldm_x4t(uint32_t* r, uint32_t addr) {
    asm volatile("ldmatrix.sync.aligned.m8n8.x4.trans.shared.b16 {%0,%1,%2,%3}, [%4];"
                 : "=r"(r[0]), "=r"(r[1]), "=r"(r[2]), "=r"(r[3]) : "r"(addr));
}
__device__ __forceinline__ void mma_f16(float* c, const uint32_t* a, const uint32_t* b) {
    asm volatile("mma.sync.aligned.m16n8k16.row.col.f32.f16.f16.f32 "
                 "{%0,%1,%2,%3}, {%4,%5,%6,%7}, {%8,%9}, {%0,%1,%2,%3};"
                 : "+f"(c[0]), "+f"(c[1]), "+f"(c[2]), "+f"(c[3])
                 : "r"(a[0]), "r"(a[1]), "r"(a[2]), "r"(a[3]), "r"(b[0]), "r"(b[1]));
}
__device__ __forceinline__ uint32_t h2u(__half2 h) { return *reinterpret_cast<uint32_t*>(&h); }

#define SCALE_F 11.313708498984761f   // sqrt(2*dh)

// ---------------------------------------------------------------------------
// Fused prep: pe + w_pos split + w_tok split + layernorm (all independent)
// ---------------------------------------------------------------------------
__device__ __forceinline__ void split4_body(const float4* __restrict__ src,
                                            uint32_t* __restrict__ hi,
                                            uint32_t* __restrict__ lo, int i) {
    float4 v = src[i];
    __half2 h0 = __floats2half2_rn(v.x, v.y);
    __half2 h1 = __floats2half2_rn(v.z, v.w);
    __half2 l0 = __floats2half2_rn(v.x - __low2float(h0), v.y - __high2float(h0));
    __half2 l1 = __floats2half2_rn(v.z - __low2float(h1), v.w - __high2float(h1));
    hi[2 * i] = h2u(h0); hi[2 * i + 1] = h2u(h1);
    lo[2 * i] = h2u(l0); lo[2 * i + 1] = h2u(l1);
}

__global__ void __launch_bounds__(256) prep_kernel(const float* __restrict__ w_pos,
                                                   const float* __restrict__ w_tok,
                                                   const float* __restrict__ x,
                                                   const float* __restrict__ gamma,
                                                   const float* __restrict__ beta) {
    const int bx = blockIdx.x, t = threadIdx.x;
    if (bx < 1024) {
        int s = bx;
        for (int d = t; d < D_MOD; d += 256) {
            int i = d >> 1;
            float div = expf((float)(2 * i) * (-9.210340371976184f / (float)D_MOD));
            float ang = (float)s * div;
            float v = (d & 1) ? cosf(ang) : sinf(ang);
            __half h = __float2half_rn(v);
            g_pe_hi[s * D_MOD + d] = h;
            g_pe_lo[s * D_MOD + d] = __float2half_rn(v - __half2float(h));
        }
    } else if (bx < 3072) {
        split4_body((const float4*)w_pos, (uint32_t*)g_wpos_hi, (uint32_t*)g_wpos_lo,
                    (bx - 1024) * 256 + t);
    } else if (bx < 6144) {
        split4_body((const float4*)w_tok, (uint32_t*)g_wtok_hi, (uint32_t*)g_wtok_lo,
                    (bx - 3072) * 256 + t);
    } else {
        const int row = bx - 6144;
        const float* xr = x + (size_t)row * D_MOD;
        const int lane = t & 31, wid = t >> 5;
        __shared__ float red[8];

        float v[4];
        float s = 0.f;
#pragma unroll
        for (int i = 0; i < 4; i++) { v[i] = xr[t + i * 256]; s += v[i]; }
#pragma unroll
        for (int o = 16; o > 0; o >>= 1) s += __shfl_xor_sync(0xffffffffu, s, o);
        if (lane == 0) red[wid] = s;
        __syncthreads();
        float tot = 0.f;
#pragma unroll
        for (int i = 0; i < 8; i++) tot += red[i];
        float mean = tot * (1.f / 1024.f);

        float sq = 0.f;
#pragma unroll
        for (int i = 0; i < 4; i++) { float d = v[i] - mean; sq += d * d; }
#pragma unroll
        for (int o = 16; o > 0; o >>= 1) sq += __shfl_xor_sync(0xffffffffu, sq, o);
        __syncthreads();
        if (lane == 0) red[wid] = sq;
        __syncthreads();
        float tot2 = 0.f;
#pragma unroll
        for (int i = 0; i < 8; i++) tot2 += red[i];
        float rstd = rsqrtf(tot2 * (1.f / 1024.f) + 1e-5f);

#pragma unroll
        for (int i = 0; i < 4; i++) {
            int c = t + i * 256;
            float y = (v[i] - mean) * rstd * gamma[c] + beta[c];
            __half h = __float2half_rn(y);
            g_xn_hi[(size_t)row * D_MOD + c] = h;
            g_xn_lo[(size_t)row * D_MOD + c] = __float2half_rn(y - __half2float(h));
        }
    }
}

// ---------------------------------------------------------------------------
// mma.sync fp16x2-split NT GEMM: 3-stage cp.async pipeline, XOR bank swizzle
// (64B rows, chunk permutation c ^= (row>>1)&3; conflict-free stores + LDSM)
// ---------------------------------------------------------------------------
#define OPBUF 8192                 // 128 rows x 64 B
#define STAGEB (4 * OPBUF)         // 32 KB
#define GEMM_SMEM (3 * STAGEB)     // 96 KB -> occ 2

__device__ __forceinline__ uint32_t gsw(int row, int chunk) {
    return (uint32_t)(row * 64 + ((chunk ^ ((row >> 1) & 3)) << 4));
}

__device__ __forceinline__ void gemm_ld_chunk(const __half* const* srcs, const int* rows0,
                                              int K, int k0, uint32_t stage_base,
                                              bool full, int tid) {
#pragma unroll
    for (int op = 0; op < 4; op++) {
        if (op == 1 && !full) continue;
#pragma unroll
        for (int it = 0; it < 2; it++) {
            int e = tid + (it << 8);
            int r = e >> 2, cs = e & 3;
            cp_async16(stage_base + op * OPBUF + gsw(r, cs),
                       srcs[op] + (size_t)(rows0[op] + r) * K + k0 + (cs << 3));
        }
    }
    CP_COMMIT();
}

__device__ __forceinline__ void gemm_body(
    const __half* __restrict__ Ahi, const __half* __restrict__ Alo,
    const __half* __restrict__ Bhi, const __half* __restrict__ Blo,
    __half* __restrict__ Chi, __half* __restrict__ Clo,
    int N, int K, int m0, int n0, bool full, char* sm)
{
    const uint32_t sb = smem_u32(sm);
    const int tid = threadIdx.x;
    const int lane = tid & 31, wid = tid >> 5;
    const int wm = wid >> 2, wn = wid & 3;

    float acc[4][4][4];
#pragma unroll
    for (int i = 0; i < 4; i++)
#pragma unroll
        for (int j = 0; j < 4; j++)
#pragma unroll
            for (int r = 0; r < 4; r++) acc[i][j][r] = 0.f;

    const __half* srcs[4] = {Ahi, Alo, Bhi, Blo};
    const int rows0[4] = {m0, m0, n0, n0};
    const int NCH = K >> 5;                 // 32 chunks of BK=32
    const int lj = lane >> 3, lr = lane & 7;

    // prologue: chunks 0 and 1
    gemm_ld_chunk(srcs, rows0, K, 0, sb, full, tid);
    gemm_ld_chunk(srcs, rows0, K, 32, sb + STAGEB, full, tid);

    for (int i = 0; i < NCH; i++) {
        if (i + 2 < NCH) {
            CP_WAIT(1);                      // chunk i resident (i+1 in flight)
            __syncthreads();                 // all warps done with chunk i-1's slot
            gemm_ld_chunk(srcs, rows0, K, (i + 2) << 5,
                          sb + ((i + 2) % 3) * STAGEB, full, tid);
        } else {
            CP_WAIT(0);
            __syncthreads();
        }

        const uint32_t st_b = sb + (i % 3) * STAGEB;
        const uint32_t ah_b = st_b;
        const uint32_t al_b = st_b + OPBUF;
        const uint32_t bh_b = st_b + 2 * OPBUF;
        const uint32_t bl_b = st_b + 3 * OPBUF;

#pragma unroll
        for (int kk = 0; kk < 32; kk += 16) {
            uint32_t ah[4][4], al[4][4];
            const int kca = (kk + (lj >> 1) * 8) >> 3;
#pragma unroll
            for (int tm = 0; tm < 4; tm++) {
                int m = wm * 64 + tm * 16 + (lj & 1) * 8 + lr;
                uint32_t off = gsw(m, kca);
                ldm_x4(ah[tm], ah_b + off);
                if (full) ldm_x4(al[tm], al_b + off);
            }
            uint32_t bh[2][4], bl[2][4];
            const int kcb = (kk + (lj & 1) * 8) >> 3;
#pragma unroll
            for (int tn = 0; tn < 2; tn++) {
                int n = wn * 32 + tn * 16 + (lj >> 1) * 8 + lr;
                uint32_t off = gsw(n, kcb);
                ldm_x4(bh[tn], bh_b + off);
                ldm_x4(bl[tn], bl_b + off);
            }
#pragma unroll
            for (int tm = 0; tm < 4; tm++)
#pragma unroll
                for (int t8 = 0; t8 < 4; t8++) {
                    uint32_t bhr[2] = {bh[t8 >> 1][2 * (t8 & 1)], bh[t8 >> 1][2 * (t8 & 1) + 1]};
                    uint32_t blr[2] = {bl[t8 >> 1][2 * (t8 & 1)], bl[t8 >> 1][2 * (t8 & 1) + 1]};
                    mma_f16(acc[tm][t8], ah[tm], bhr);
                    mma_f16(acc[tm][t8], ah[tm], blr);
                    if (full) mma_f16(acc[tm][t8], al[tm], bhr);
                }
        }
    }

#pragma unroll
    for (int tm = 0; tm < 4; tm++) {
        int m = m0 + wm * 64 + tm * 16 + (lane >> 2);
#pragma unroll
        for (int t8 = 0; t8 < 4; t8++) {
            int n = n0 + wn * 32 + t8 * 8 + 2 * (lane & 3);
            float v0 = acc[tm][t8][0], v1 = acc[tm][t8][1];
            float v2 = acc[tm][t8][2], v3 = acc[tm][t8][3];
            __half2 h01 = __floats2half2_rn(v0, v1);
            __half2 h23 = __floats2half2_rn(v2, v3);
            *(__half2*)(Chi + (size_t)m * N + n) = h01;
            *(__half2*)(Chi + (size_t)(m + 8) * N + n) = h23;
            if (full) {
                __half2 l01 = __floats2half2_rn(v0 - __low2float(h01), v1 - __high2float(h01));
                __half2 l23 = __floats2half2_rn(v2 - __low2float(h23), v3 - __high2float(h23));
                *(__half2*)(Clo + (size_t)m * N + n) = l01;
                *(__half2*)(Clo + (size_t)(m + 8) * N + n) = l23;
            }
        }
    }
}

// merged launch: blocks [0,768) = tok (24 x 32), blocks [768,896) = pos (16 x 8)
__global__ void __launch_bounds__(256) gemm_merged() {
    extern __shared__ char sm[];
    int bx = blockIdx.x;
    if (bx < 768) {
        int n0 = (bx % 24) * 128, m0 = (bx / 24) * 128;
        gemm_body(g_xn_hi, g_xn_lo, g_wtok_hi, g_wtok_lo, g_th, g_tl,
                  3 * D_MOD, D_MOD, m0, n0, n0 < 2 * D_MOD, sm);
    } else {
        int bp = bx - 768;
        int n0 = (bp % 16) * 128, m0 = (bp / 16) * 128;
        gemm_body(g_pe_hi, g_pe_lo, g_wpos_hi, g_wpos_lo, g_ph, g_pl,
                  2 * D_MOD, D_MOD, m0, n0, true, sm);
    }
}

// ---------------------------------------------------------------------------
// P0[h,q,k] = (pos_q . pos_k) * SCALE + bias_table[k-q+1024, h]
// ---------------------------------------------------------------------------
#define PA_SMEM (4 * 18432 + 1024)

__global__ void __launch_bounds__(256) posattn_kernel(const float* __restrict__ bias_table) {
    extern __shared__ char sm[];
    const uint32_t sb = smem_u32(sm);
    const int tid = threadIdx.x, lane = tid & 31, wid = tid >> 5;
    const int wm = wid >> 2, wn = wid & 3;
    const int h = blockIdx.z, q0 = blockIdx.y * 128, k0 = blockIdx.x * 128;
    const int hc = h * 64;
    const int lj = lane >> 3, lr = lane & 7;

#pragma unroll
    for (int it = 0; it < 4; it++) {
        int e = tid + (it << 8);
        int r = e >> 3, c = e & 7;
        size_t qa = (size_t)(q0 + r) * 2048 + 1024 + hc + c * 8;
        size_t ka = (size_t)(k0 + r) * 2048 + hc + c * 8;
        uint32_t o = r * 144 + c * 16;
        cp_async16(sb + o, g_ph + qa);
        cp_async16(sb + 18432 + o, g_pl + qa);
        cp_async16(sb + 36864 + o, g_ph + ka);
        cp_async16(sb + 55296 + o, g_pl + ka);
    }
    {
        int rel = k0 - q0 + 897 + tid;
        rel = rel < 0 ? 0 : (rel > 2047 ? 2047 : rel);
        cp_async4(sb + 73728 + tid * 4, bias_table + rel * N_H + h);
    }
    CP_COMMIT();
    CP_WAIT(0);
    __syncthreads();

    float acc[4][4][4];
#pragma unroll
    for (int i = 0; i < 4; i++)
#pragma unroll
        for (int j = 0; j < 4; j++)
#pragma unroll
            for (int r = 0; r < 4; r++) acc[i][j][r] = 0.f;

#pragma unroll
    for (int kk = 0; kk < 4; kk++) {
        uint32_t ah[4][4], al[4][4];
#pragma unroll
        for (int tm = 0; tm < 4; tm++) {
            int m = wm * 64 + tm * 16 + (lj & 1) * 8 + lr;
            int k = kk * 16 + (lj >> 1) * 8;
            ldm_x4(ah[tm], sb + m * 144 + k * 2);
            ldm_x4(al[tm], sb + 18432 + m * 144 + k * 2);
        }
        uint32_t bh[2][4], bl[2][4];
#pragma unroll
        for (int tn = 0; tn < 2; tn++) {
            int n = wn * 32 + tn * 16 + (lj >> 1) * 8 + lr;
            int k = kk * 16 + (lj & 1) * 8;
            ldm_x4(bh[tn], sb + 36864 + n * 144 + k * 2);
            ldm_x4(bl[tn], sb + 55296 + n * 144 + k * 2);
        }
#pragma unroll
        for (int tm = 0; tm < 4; tm++)
#pragma unroll
            for (int t8 = 0; t8 < 4; t8++) {
                uint32_t bhr[2] = {bh[t8 >> 1][2 * (t8 & 1)], bh[t8 >> 1][2 * (t8 & 1) + 1]};
                uint32_t blr[2] = {bl[t8 >> 1][2 * (t8 & 1)], bl[t8 >> 1][2 * (t8 & 1) + 1]};
                mma_f16(acc[tm][t8], ah[tm], bhr);
                mma_f16(acc[tm][t8], ah[tm], blr);
                mma_f16(acc[tm][t8], al[tm], bhr);
            }
    }

    const float* bias_s = (const float*)(sm + 73728);
    float* P0b = g_P0 + ((size_t)h << 20);
#pragma unroll
    for (int tm = 0; tm < 4; tm++) {
        int q = wm * 64 + tm * 16 + (lane >> 2);
#pragma unroll
        for (int t8 = 0; t8 < 4; t8++) {
            int k = wn * 32 + t8 * 8 + 2 * (lane & 3);
            int idx = k - q + 127;
            float o0 = acc[tm][t8][0] * SCALE_F + bias_s[idx];
            float o1 = acc[tm][t8][1] * SCALE_F + bias_s[idx + 1];
            float o2 = acc[tm][t8][2] * SCALE_F + bias_s[idx - 8];
            float o3 = acc[tm][t8][3] * SCALE_F + bias_s[idx - 7];
            *(float2*)(P0b + (size_t)(q0 + q) * 1024 + k0 + k) = make_float2(o0, o1);
            *(float2*)(P0b + (size_t)(q0 + q + 8) * 1024 + k0 + k) = make_float2(o2, o3);
        }
    }
}

// ---------------------------------------------------------------------------
// Tensor-core flash attention (R10 best config): de=64 tok-only, P0+bias
// staged via cp.async into smem, occ 2. QK 3-pass, PV 1-pass.
// ---------------------------------------------------------------------------
#define KROW2 144
#define KB2 9216
#define P0ROW 272
#define STG (3 * KB2 + 64 * P0ROW)   // 45056
#define FL_SMEM (2 * STG)            // 90112

__device__ __forceinline__ void fl_prefetch_tile(uint32_t sb, int b, int h, int hc,
                                                 int q0, int k0, int s, int tid) {
    const uint32_t kb = sb + s * STG;
    const size_t rb = ((size_t)b * S_LEN + k0) * 3072;
#pragma unroll
    for (int it = 0; it < 4; it++) {
        int e = tid + (it << 7);
        int k = e >> 3, c = e & 7;
        size_t so = rb + (size_t)k * 3072 + hc + c * 8;
        uint32_t o = k * KROW2 + c * 16;
        cp_async16(kb + o, g_th + so);
        cp_async16(kb + KB2 + o, g_tl + so);
        size_t sv = rb + (size_t)k * 3072 + 2048 + hc + c * 8;
        cp_async16(kb + 2 * KB2 + o, g_th + sv);
    }
    const float* p0src = g_P0 + ((size_t)h << 20) + (size_t)q0 * 1024 + k0;
#pragma unroll
    for (int it = 0; it < 8; it++) {
        int e = tid + (it << 7);
        int r = e >> 4, c = e & 15;
        cp_async16(kb + 3 * KB2 + r * P0ROW + c * 16, p0src + (size_t)r * 1024 + c * 4);
    }
}

__global__ void __launch_bounds__(128, 2) flash_kernel(float* __restrict__ out) {
    extern __shared__ char sm[];
    const uint32_t sb = smem_u32(sm);
    const int tid = threadIdx.x, lane = tid & 31, wid = tid >> 5;
    const int lj = lane >> 3, lr = lane & 7;
    const int b = blockIdx.z, h = blockIdx.y, q0 = blockIdx.x * 64;
    const int hc = h * 64;
    const int m0w = wid * 16;

    {
        const size_t rb = ((size_t)b * S_LEN + q0) * 3072;
#pragma unroll
        for (int it = 0; it < 4; it++) {
            int e = tid + (it << 7);
            int q = e >> 3, c = e & 7;
            size_t so = rb + (size_t)q * 3072 + 1024 + hc + c * 8;
            cp_async16(sb + q * KROW2 + c * 16, g_th + so);
            cp_async16(sb + STG + q * KROW2 + c * 16, g_tl + so);
        }
        CP_COMMIT();
        CP_WAIT(0);
        __syncthreads();
    }
    uint32_t qh[4][4], qlo[4][4];
#pragma unroll
    for (int dk = 0; dk < 4; dk++) {
        uint32_t qa = sb + (m0w + (lj & 1) * 8 + lr) * KROW2 + (dk * 16 + (lj >> 1) * 8) * 2;
        ldm_x4(qh[dk], qa);
        ldm_x4(qlo[dk], qa + STG);
    }
    __syncthreads();

    fl_prefetch_tile(sb, b, h, hc, q0, 0, 0, tid);
    CP_COMMIT();

    float O[8][4];
#pragma unroll
    for (int i = 0; i < 8; i++)
#pragma unroll
        for (int j = 0; j < 4; j++) O[i][j] = 0.f;
    float m0 = -INFINITY, m1 = -INFINITY, l0 = 0.f, l1 = 0.f;

    const float LOG2E = 1.4426950408889634f;
    const int NT = S_LEN / 64;

    for (int kt = 0; kt < NT; kt++) {
        const int s = kt & 1;
        if (kt + 1 < NT) {
            fl_prefetch_tile(sb, b, h, hc, q0, (kt + 1) * 64, s ^ 1, tid);
            CP_COMMIT();
            CP_WAIT(1);
        } else {
            CP_WAIT(0);
        }
        __syncthreads();

        const uint32_t khb = sb + s * STG;
        const uint32_t vhb = khb + 2 * KB2;
        const char* p0s = sm + s * STG + 3 * KB2;

        float Sa[8][4];
#pragma unroll
        for (int i = 0; i < 8; i++)
#pragma unroll
            for (int j = 0; j < 4; j++) Sa[i][j] = 0.f;

#pragma unroll
        for (int dk = 0; dk < 4; dk++) {
#pragma unroll
            for (int ng = 0; ng < 4; ng++) {
                uint32_t bh[4], bl[4];
                uint32_t ka = khb + (ng * 16 + (lj >> 1) * 8 + lr) * KROW2 + (dk * 16 + (lj & 1) * 8) * 2;
                ldm_x4(bh, ka);
                ldm_x4(bl, ka + KB2);
                uint32_t b0[2] = {bh[0], bh[1]}, c0[2] = {bl[0], bl[1]};
                mma_f16(Sa[2 * ng], qh[dk], b0);
                mma_f16(Sa[2 * ng], qh[dk], c0);
                mma_f16(Sa[2 * ng], qlo[dk], b0);
                uint32_t b1[2] = {bh[2], bh[3]}, c1[2] = {bl[2], bl[3]};
                mma_f16(Sa[2 * ng + 1], qh[dk], b1);
                mma_f16(Sa[2 * ng + 1], qh[dk], c1);
                mma_f16(Sa[2 * ng + 1], qlo[dk], b1);
            }
        }

        const int qr = m0w + (lane >> 2);
        float mx0 = -INFINITY, mx1 = -INFINITY;
#pragma unroll
        for (int tt = 0; tt < 8; tt++) {
            int kl = 8 * tt + 2 * (lane & 3);
            float2 b0 = *(const float2*)(p0s + qr * P0ROW + kl * 4);
            float2 b1 = *(const float2*)(p0s + (qr + 8) * P0ROW + kl * 4);
            float s0 = Sa[tt][0] * SCALE_F + b0.x;
            float s1 = Sa[tt][1] * SCALE_F + b0.y;
            float s2 = Sa[tt][2] * SCALE_F + b1.x;
            float s3 = Sa[tt][3] * SCALE_F + b1.y;
            Sa[tt][0] = s0; Sa[tt][1] = s1; Sa[tt][2] = s2; Sa[tt][3] = s3;
            mx0 = fmaxf(mx0, fmaxf(s0, s1));
            mx1 = fmaxf(mx1, fmaxf(s2, s3));
        }
        mx0 = fmaxf(mx0, __shfl_xor_sync(0xffffffffu, mx0, 1));
        mx0 = fmaxf(mx0, __shfl_xor_sync(0xffffffffu, mx0, 2));
        mx1 = fmaxf(mx1, __shfl_xor_sync(0xffffffffu, mx1, 1));
        mx1 = fmaxf(mx1, __shfl_xor_sync(0xffffffffu, mx1, 2));
        float mn0 = fmaxf(m0, mx0), mn1 = fmaxf(m1, mx1);
        float a0 = exp2f((m0 - mn0) * LOG2E), a1 = exp2f((m1 - mn1) * LOG2E);
        m0 = mn0; m1 = mn1;

        uint32_t ph0[8], ph1[8];
        float r0 = 0.f, r1 = 0.f;
#pragma unroll
        for (int tt = 0; tt < 8; tt++) {
            float p0 = exp2f((Sa[tt][0] - m0) * LOG2E);
            float p1 = exp2f((Sa[tt][1] - m0) * LOG2E);
            float p2 = exp2f((Sa[tt][2] - m1) * LOG2E);
            float p3 = exp2f((Sa[tt][3] - m1) * LOG2E);
            r0 += p0 + p1; r1 += p2 + p3;
            ph0[tt] = h2u(__floats2half2_rn(p0, p1));
            ph1[tt] = h2u(__floats2half2_rn(p2, p3));
        }
        r0 += __shfl_xor_sync(0xffffffffu, r0, 1);
        r0 += __shfl_xor_sync(0xffffffffu, r0, 2);
        r1 += __shfl_xor_sync(0xffffffffu, r1, 1);
        r1 += __shfl_xor_sync(0xffffffffu, r1, 2);
        l0 = l0 * a0 + r0;
        l1 = l1 * a1 + r1;
#pragma unroll
        for (int dt = 0; dt < 8; dt++) {
            O[dt][0] *= a0; O[dt][1] *= a0; O[dt][2] *= a1; O[dt][3] *= a1;
        }

#pragma unroll
        for (int ck = 0; ck < 4; ck++) {
            uint32_t Ah[4] = {ph0[2 * ck], ph1[2 * ck], ph0[2 * ck + 1], ph1[2 * ck + 1]};
#pragma unroll
            for (int dg = 0; dg < 4; dg++) {
                uint32_t vh[4];
                uint32_t va = vhb + (ck * 16 + (lj & 1) * 8 + lr) * KROW2 + (dg * 16 + (lj >> 1) * 8) * 2;
                ldm_x4t(vh, va);
                uint32_t v0[2] = {vh[0], vh[1]};
                mma_f16(O[2 * dg], Ah, v0);
                uint32_t v1[2] = {vh[2], vh[3]};
                mma_f16(O[2 * dg + 1], Ah, v1);
            }
        }
        __syncthreads();
    }

    float inv0 = 1.f / l0, inv1 = 1.f / l1;
    size_t row = (size_t)b * S_LEN + q0 + m0w + (lane >> 2);
#pragma unroll
    for (int dt = 0; dt < 8; dt++) {
        int n = hc + dt * 8 + 2 * (lane & 3);
        *(float2*)(out + row * D_MOD + n) = make_float2(O[dt][0] * inv0, O[dt][1] * inv0);
        *(float2*)(out + (row + 8) * D_MOD + n) = make_float2(O[dt][2] * inv1, O[dt][3] * inv1);
    }
}

// ---------------------------------------------------------------------------
// Launch (single stream — block-range fusion)
// ---------------------------------------------------------------------------
extern "C" void kernel_launch(void* const* d_in, const int* in_sizes, int n_in,
                              void* d_out, int out_size) {
    const float* x          = (const float*)d_in[0];
    const float* gamma      = (const float*)d_in[1];
    const float* beta       = (const float*)d_in[2];
    const float* w_pos      = (const float*)d_in[3];
    const float* w_tok      = (const float*)d_in[4];
    const float* bias_table = (const float*)d_in[5];
    float* out = (float*)d_out;

    cudaFuncSetAttribute(gemm_merged, cudaFuncAttributeMaxDynamicSharedMemorySize, GEMM_SMEM);
    cudaFuncSetAttribute(posattn_kernel, cudaFuncAttributeMaxDynamicSharedMemorySize, PA_SMEM);
    cudaFuncSetAttribute(flash_kernel, cudaFuncAttributeMaxDynamicSharedMemorySize, FL_SMEM);

    // fused elementwise: pe + w_pos split + w_tok split + layernorm
    prep_kernel<<<10240, 256>>>(w_pos, w_tok, x, gamma, beta);
    // merged GEMMs: tok (768 blocks) + pos (128 blocks), 3-stage pipeline
    gemm_merged<<<896, 256, GEMM_SMEM>>>();
    // P0 = pos_attn*SCALE + bias (batch-independent)
    posattn_kernel<<<dim3(8, 8, 16), 256, PA_SMEM>>>(bias_table);
    // flash attention (R10 config: de=64, P0 smem-staged, occ 2)
    flash_kernel<<<dim3(S_LEN / 64, N_H, B_SZ), 128, FL_SMEM>>>(out);
}

// round 14
// speedup vs baseline: 1.0102x; 1.0102x over previous
#include <cuda_runtime.h>
#include <cuda_fp16.h>
#include <math.h>
#include <stdint.h>

#define S_LEN 1024
#define D_MOD 1024
#define B_SZ 4
#define N_H 16
#define MAXLEN 1024

// ---------------------------------------------------------------------------
// Scratch (device globals — no allocations allowed)
// ---------------------------------------------------------------------------
__device__ __half g_pe_hi[S_LEN * D_MOD],        g_pe_lo[S_LEN * D_MOD];
__device__ __half g_wpos_hi[2 * D_MOD * D_MOD],  g_wpos_lo[2 * D_MOD * D_MOD];
__device__ __half g_xn_hi[B_SZ * S_LEN * D_MOD], g_xn_lo[B_SZ * S_LEN * D_MOD];
__device__ __half g_wtok_hi[3 * D_MOD * D_MOD],  g_wtok_lo[3 * D_MOD * D_MOD];
__device__ __half g_ph[S_LEN * 2 * D_MOD], g_pl[S_LEN * 2 * D_MOD];                      // pos
__device__ __half g_th[(size_t)B_SZ * S_LEN * 3 * D_MOD], g_tl[(size_t)B_SZ * S_LEN * 3 * D_MOD]; // tok
__device__ float  g_P0[(size_t)N_H * S_LEN * S_LEN];      // pos_attn*SCALE + bias, 67MB

// ---------------------------------------------------------------------------
// helpers
// ---------------------------------------------------------------------------
__device__ __forceinline__ uint32_t smem_u32(const void* p) {
    uint32_t a;
    asm("{ .reg .u64 t; cvta.to.shared.u64 t, %1; cvt.u32.u64 %0, t; }" : "=r"(a) : "l"(p));
    return a;
}
__device__ __forceinline__ void cp_async16(uint32_t dst, const void* src) {
    asm volatile("cp.async.cg.shared.global [%0], [%1], 16;" :: "r"(dst), "l"(src) : "memory");
}
__device__ __forceinline__ void cp_async4(uint32_t dst, const void* src) {
    asm volatile("cp.async.ca.shared.global [%0], [%1], 4;" :: "r"(dst), "l"(src) : "memory");
}
#define CP_COMMIT() asm volatile("cp.async.commit_group;" ::: "memory")
#define CP_WAIT(n)  asm volatile("cp.async.wait_group %0;" :: "n"(n) : "memory")

__device__ __forceinline__ void ldm_x4(uint32_t* r, uint32_t addr) {
    asm volatile("ldmatrix.sync.aligned.m8n8.x4.shared.b16 {%0,%1,%2,%3}, [%4];"
                 : "=r"(r[0]), "=r"(r[1]), "=r"(r[2]), "=r"(r[3]) : "r"(addr));
}
__device__ __forceinline__ void ldm_x4t(uint32_t* r, uint32_t addr) {
    asm volatile("ldmatrix.sync.aligned.m8n8.x4.trans.shared.b16 {%0,%1,%2,%3}, [%4];"
                 : "=r"(r[0]), "=r"(r[1]), "=r"(r[2]), "=r"(r[3]) : "r"(addr));
}
__device__ __forceinline__ void mma_f16(float* c, const uint32_t* a, const uint32_t* b) {
    asm volatile("mma.sync.aligned.m16n8k16.row.col.f32.f16.f16.f32 "
                 "{%0,%1,%2,%3}, {%4,%5,%6,%7}, {%8,%9}, {%0,%1,%2,%3};"
                 : "+f"(c[0]), "+f"(c[1]), "+f"(c[2]), "+f"(c[3])
                 : "r"(a[0]), "r"(a[1]), "r"(a[2]), "r"(a[3]), "r"(b[0]), "r"(b[1]));
}
__device__ __forceinline__ uint32_t h2u(__half2 h) { return *reinterpret_cast<uint32_t*>(&h); }

#define SCALE_F 11.313708498984761f   // sqrt(2*dh)

// ---------------------------------------------------------------------------
// Fused prep: pe + w_pos split + w_tok split + layernorm (all independent)
// ---------------------------------------------------------------------------
__device__ __forceinline__ void split4_body(const float4* __restrict__ src,
                                            uint32_t* __restrict__ hi,
                                            uint32_t* __restrict__ lo, int i) {
    float4 v = src[i];
    __half2 h0 = __floats2half2_rn(v.x, v.y);
    __half2 h1 = __floats2half2_rn(v.z, v.w);
    __half2 l0 = __floats2half2_rn(v.x - __low2float(h0), v.y - __high2float(h0));
    __half2 l1 = __floats2half2_rn(v.z - __low2float(h1), v.w - __high2float(h1));
    hi[2 * i] = h2u(h0); hi[2 * i + 1] = h2u(h1);
    lo[2 * i] = h2u(l0); lo[2 * i + 1] = h2u(l1);
}

__global__ void __launch_bounds__(256) prep_kernel(const float* __restrict__ w_pos,
                                                   const float* __restrict__ w_tok,
                                                   const float* __restrict__ x,
                                                   const float* __restrict__ gamma,
                                                   const float* __restrict__ beta) {
    const int bx = blockIdx.x, t = threadIdx.x;
    if (bx < 1024) {
        int s = bx;
        for (int d = t; d < D_MOD; d += 256) {
            int i = d >> 1;
            float div = expf((float)(2 * i) * (-9.210340371976184f / (float)D_MOD));
            float ang = (float)s * div;
            float v = (d & 1) ? cosf(ang) : sinf(ang);
            __half h = __float2half_rn(v);
            g_pe_hi[s * D_MOD + d] = h;
            g_pe_lo[s * D_MOD + d] = __float2half_rn(v - __half2float(h));
        }
    } else if (bx < 3072) {
        split4_body((const float4*)w_pos, (uint32_t*)g_wpos_hi, (uint32_t*)g_wpos_lo,
                    (bx - 1024) * 256 + t);
    } else if (bx < 6144) {
        split4_body((const float4*)w_tok, (uint32_t*)g_wtok_hi, (uint32_t*)g_wtok_lo,
                    (bx - 3072) * 256 + t);
    } else {
        const int row = bx - 6144;
        const float* xr = x + (size_t)row * D_MOD;
        const int lane = t & 31, wid = t >> 5;
        __shared__ float red[8];

        float v[4];
        float s = 0.f;
#pragma unroll
        for (int i = 0; i < 4; i++) { v[i] = xr[t + i * 256]; s += v[i]; }
#pragma unroll
        for (int o = 16; o > 0; o >>= 1) s += __shfl_xor_sync(0xffffffffu, s, o);
        if (lane == 0) red[wid] = s;
        __syncthreads();
        float tot = 0.f;
#pragma unroll
        for (int i = 0; i < 8; i++) tot += red[i];
        float mean = tot * (1.f / 1024.f);

        float sq = 0.f;
#pragma unroll
        for (int i = 0; i < 4; i++) { float d = v[i] - mean; sq += d * d; }
#pragma unroll
        for (int o = 16; o > 0; o >>= 1) sq += __shfl_xor_sync(0xffffffffu, sq, o);
        __syncthreads();
        if (lane == 0) red[wid] = sq;
        __syncthreads();
        float tot2 = 0.f;
#pragma unroll
        for (int i = 0; i < 8; i++) tot2 += red[i];
        float rstd = rsqrtf(tot2 * (1.f / 1024.f) + 1e-5f);

#pragma unroll
        for (int i = 0; i < 4; i++) {
            int c = t + i * 256;
            float y = (v[i] - mean) * rstd * gamma[c] + beta[c];
            __half h = __float2half_rn(y);
            g_xn_hi[(size_t)row * D_MOD + c] = h;
            g_xn_lo[(size_t)row * D_MOD + c] = __float2half_rn(y - __half2float(h));
        }
    }
}

// ---------------------------------------------------------------------------
// mma.sync fp16x2-split NT GEMM (R10-proven: 80B padded rows, 2-stage,
// issue-then-wait). 128-row and 64-row M-tile variants.
// ---------------------------------------------------------------------------
#define OPBUF 10240
#define GEMM_SMEM (8 * OPBUF)

// 128x128 tile body (verbatim R10)
__device__ __forceinline__ void gemm_body(
    const __half* __restrict__ Ahi, const __half* __restrict__ Alo,
    const __half* __restrict__ Bhi, const __half* __restrict__ Blo,
    __half* __restrict__ Chi, __half* __restrict__ Clo,
    int N, int K, int m0, int n0, bool full, char* sm)
{
    const uint32_t sb = smem_u32(sm);
    const int tid = threadIdx.x;
    const int lane = tid & 31, wid = tid >> 5;
    const int wm = wid >> 2, wn = wid & 3;

    float acc[4][4][4];
#pragma unroll
    for (int i = 0; i < 4; i++)
#pragma unroll
        for (int j = 0; j < 4; j++)
#pragma unroll
            for (int r = 0; r < 4; r++) acc[i][j][r] = 0.f;

    const __half* srcs[4] = {Ahi, Alo, Bhi, Blo};
    const int rows0[4] = {m0, m0, n0, n0};
    const int NCH = K >> 5;
    const int lj = lane >> 3, lr = lane & 7;

#pragma unroll
    for (int op = 0; op < 4; op++) {
        if (op == 1 && !full) continue;
#pragma unroll
        for (int it = 0; it < 2; it++) {
            int e = tid + (it << 8);
            int r = e >> 2, cs = e & 3;
            cp_async16(sb + op * OPBUF + r * 80 + cs * 16,
                       srcs[op] + (size_t)(rows0[op] + r) * K + (cs << 3));
        }
    }
    CP_COMMIT();

    for (int i = 0; i < NCH; i++) {
        const int s = i & 1;
        if (i + 1 < NCH) {
            const int s2 = s ^ 1, k0 = (i + 1) << 5;
#pragma unroll
            for (int op = 0; op < 4; op++) {
                if (op == 1 && !full) continue;
#pragma unroll
                for (int it = 0; it < 2; it++) {
                    int e = tid + (it << 8);
                    int r = e >> 2, cs = e & 3;
                    cp_async16(sb + (s2 * 4 + op) * OPBUF + r * 80 + cs * 16,
                               srcs[op] + (size_t)(rows0[op] + r) * K + k0 + (cs << 3));
                }
            }
            CP_COMMIT();
            CP_WAIT(1);
        } else {
            CP_WAIT(0);
        }
        __syncthreads();

        const uint32_t ah_b = sb + (s * 4 + 0) * OPBUF;
        const uint32_t al_b = sb + (s * 4 + 1) * OPBUF;
        const uint32_t bh_b = sb + (s * 4 + 2) * OPBUF;
        const uint32_t bl_b = sb + (s * 4 + 3) * OPBUF;

#pragma unroll
        for (int kk = 0; kk < 32; kk += 16) {
            uint32_t ah[4][4], al[4][4];
#pragma unroll
            for (int tm = 0; tm < 4; tm++) {
                int m = wm * 64 + tm * 16 + (lj & 1) * 8 + lr;
                int k = kk + (lj >> 1) * 8;
                ldm_x4(ah[tm], ah_b + m * 80 + k * 2);
                if (full) ldm_x4(al[tm], al_b + m * 80 + k * 2);
            }
            uint32_t bh[2][4], bl[2][4];
#pragma unroll
            for (int tn = 0; tn < 2; tn++) {
                int n = wn * 32 + tn * 16 + (lj >> 1) * 8 + lr;
                int k = kk + (lj & 1) * 8;
                ldm_x4(bh[tn], bh_b + n * 80 + k * 2);
                ldm_x4(bl[tn], bl_b + n * 80 + k * 2);
            }
#pragma unroll
            for (int tm = 0; tm < 4; tm++)
#pragma unroll
                for (int t8 = 0; t8 < 4; t8++) {
                    uint32_t bhr[2] = {bh[t8 >> 1][2 * (t8 & 1)], bh[t8 >> 1][2 * (t8 & 1) + 1]};
                    uint32_t blr[2] = {bl[t8 >> 1][2 * (t8 & 1)], bl[t8 >> 1][2 * (t8 & 1) + 1]};
                    mma_f16(acc[tm][t8], ah[tm], bhr);
                    mma_f16(acc[tm][t8], ah[tm], blr);
                    if (full) mma_f16(acc[tm][t8], al[tm], bhr);
                }
        }
        __syncthreads();
    }

#pragma unroll
    for (int tm = 0; tm < 4; tm++) {
        int m = m0 + wm * 64 + tm * 16 + (lane >> 2);
#pragma unroll
        for (int t8 = 0; t8 < 4; t8++) {
            int n = n0 + wn * 32 + t8 * 8 + 2 * (lane & 3);
            float v0 = acc[tm][t8][0], v1 = acc[tm][t8][1];
            float v2 = acc[tm][t8][2], v3 = acc[tm][t8][3];
            __half2 h01 = __floats2half2_rn(v0, v1);
            __half2 h23 = __floats2half2_rn(v2, v3);
            *(__half2*)(Chi + (size_t)m * N + n) = h01;
            *(__half2*)(Chi + (size_t)(m + 8) * N + n) = h23;
            if (full) {
                __half2 l01 = __floats2half2_rn(v0 - __low2float(h01), v1 - __high2float(h01));
                __half2 l23 = __floats2half2_rn(v2 - __low2float(h23), v3 - __high2float(h23));
                *(__half2*)(Clo + (size_t)m * N + n) = l01;
                *(__half2*)(Clo + (size_t)(m + 8) * N + n) = l23;
            }
        }
    }
}

// 64x128 tile body (half-size M jobs for tail packing; always 3-pass)
__device__ __forceinline__ void gemm_body64(
    const __half* __restrict__ Ahi, const __half* __restrict__ Alo,
    const __half* __restrict__ Bhi, const __half* __restrict__ Blo,
    __half* __restrict__ Chi, __half* __restrict__ Clo,
    int N, int K, int m0, int n0, char* sm)
{
    const uint32_t sb = smem_u32(sm);
    const int tid = threadIdx.x;
    const int lane = tid & 31, wid = tid >> 5;
    const int wm = wid >> 2, wn = wid & 3;   // 2m x 4n of 32x32

    float acc[2][4][4];
#pragma unroll
    for (int i = 0; i < 2; i++)
#pragma unroll
        for (int j = 0; j < 4; j++)
#pragma unroll
            for (int r = 0; r < 4; r++) acc[i][j][r] = 0.f;

    const int NCH = K >> 5;
    const int lj = lane >> 3, lr = lane & 7;

    // loader: A 64 rows (one pass), B 128 rows (two passes)
    {
        int r = tid >> 2, cs = tid & 3;
        cp_async16(sb + 0 * OPBUF + r * 80 + cs * 16, Ahi + (size_t)(m0 + r) * K + (cs << 3));
        cp_async16(sb + 1 * OPBUF + r * 80 + cs * 16, Alo + (size_t)(m0 + r) * K + (cs << 3));
#pragma unroll
        for (int it = 0; it < 2; it++) {
            int e = tid + (it << 8);
            int rr = e >> 2, cc = e & 3;
            cp_async16(sb + 2 * OPBUF + rr * 80 + cc * 16, Bhi + (size_t)(n0 + rr) * K + (cc << 3));
            cp_async16(sb + 3 * OPBUF + rr * 80 + cc * 16, Blo + (size_t)(n0 + rr) * K + (cc << 3));
        }
        CP_COMMIT();
    }

    for (int i = 0; i < NCH; i++) {
        const int s = i & 1;
        if (i + 1 < NCH) {
            const int s2 = s ^ 1, k0 = (i + 1) << 5;
            int r = tid >> 2, cs = tid & 3;
            cp_async16(sb + (s2 * 4 + 0) * OPBUF + r * 80 + cs * 16,
                       Ahi + (size_t)(m0 + r) * K + k0 + (cs << 3));
            cp_async16(sb + (s2 * 4 + 1) * OPBUF + r * 80 + cs * 16,
                       Alo + (size_t)(m0 + r) * K + k0 + (cs << 3));
#pragma unroll
            for (int it = 0; it < 2; it++) {
                int e = tid + (it << 8);
                int rr = e >> 2, cc = e & 3;
                cp_async16(sb + (s2 * 4 + 2) * OPBUF + rr * 80 + cc * 16,
                           Bhi + (size_t)(n0 + rr) * K + k0 + (cc << 3));
                cp_async16(sb + (s2 * 4 + 3) * OPBUF + rr * 80 + cc * 16,
                           Blo + (size_t)(n0 + rr) * K + k0 + (cc << 3));
            }
            CP_COMMIT();
            CP_WAIT(1);
        } else {
            CP_WAIT(0);
        }
        __syncthreads();

        const uint32_t ah_b = sb + (s * 4 + 0) * OPBUF;
        const uint32_t al_b = sb + (s * 4 + 1) * OPBUF;
        const uint32_t bh_b = sb + (s * 4 + 2) * OPBUF;
        const uint32_t bl_b = sb + (s * 4 + 3) * OPBUF;

#pragma unroll
        for (int kk = 0; kk < 32; kk += 16) {
            uint32_t ah[2][4], al[2][4];
#pragma unroll
            for (int tm = 0; tm < 2; tm++) {
                int m = wm * 32 + tm * 16 + (lj & 1) * 8 + lr;
                int k = kk + (lj >> 1) * 8;
                ldm_x4(ah[tm], ah_b + m * 80 + k * 2);
                ldm_x4(al[tm], al_b + m * 80 + k * 2);
            }
            uint32_t bh[2][4], bl[2][4];
#pragma unroll
            for (int tn = 0; tn < 2; tn++) {
                int n = wn * 32 + tn * 16 + (lj >> 1) * 8 + lr;
                int k = kk + (lj & 1) * 8;
                ldm_x4(bh[tn], bh_b + n * 80 + k * 2);
                ldm_x4(bl[tn], bl_b + n * 80 + k * 2);
            }
#pragma unroll
            for (int tm = 0; tm < 2; tm++)
#pragma unroll
                for (int t8 = 0; t8 < 4; t8++) {
                    uint32_t bhr[2] = {bh[t8 >> 1][2 * (t8 & 1)], bh[t8 >> 1][2 * (t8 & 1) + 1]};
                    uint32_t blr[2] = {bl[t8 >> 1][2 * (t8 & 1)], bl[t8 >> 1][2 * (t8 & 1) + 1]};
                    mma_f16(acc[tm][t8], ah[tm], bhr);
                    mma_f16(acc[tm][t8], ah[tm], blr);
                    mma_f16(acc[tm][t8], al[tm], bhr);
                }
        }
        __syncthreads();
    }

#pragma unroll
    for (int tm = 0; tm < 2; tm++) {
        int m = m0 + wm * 32 + tm * 16 + (lane >> 2);
#pragma unroll
        for (int t8 = 0; t8 < 4; t8++) {
            int n = n0 + wn * 32 + t8 * 8 + 2 * (lane & 3);
            float v0 = acc[tm][t8][0], v1 = acc[tm][t8][1];
            float v2 = acc[tm][t8][2], v3 = acc[tm][t8][3];
            __half2 h01 = __floats2half2_rn(v0, v1);
            __half2 h23 = __floats2half2_rn(v2, v3);
            __half2 l01 = __floats2half2_rn(v0 - __low2float(h01), v1 - __high2float(h01));
            __half2 l23 = __floats2half2_rn(v2 - __low2float(h23), v3 - __high2float(h23));
            *(__half2*)(Chi + (size_t)m * N + n) = h01;
            *(__half2*)(Clo + (size_t)m * N + n) = l01;
            *(__half2*)(Chi + (size_t)(m + 8) * N + n) = h23;
            *(__half2*)(Clo + (size_t)(m + 8) * N + n) = l23;
        }
    }
}

// merged launch: [0,768) tok 128x128 | [768,1024) pos 64x128 (tail packing)
__global__ void __launch_bounds__(256) gemm_merged() {
    extern __shared__ char sm[];
    int bx = blockIdx.x;
    if (bx < 768) {
        int n0 = (bx % 24) * 128, m0 = (bx / 24) * 128;
        gemm_body(g_xn_hi, g_xn_lo, g_wtok_hi, g_wtok_lo, g_th, g_tl,
                  3 * D_MOD, D_MOD, m0, n0, n0 < 2 * D_MOD, sm);
    } else {
        int bp = bx - 768;                   // 0..255
        int m0 = (bp >> 4) * 64, n0 = (bp & 15) * 128;
        gemm_body64(g_pe_hi, g_pe_lo, g_wpos_hi, g_wpos_lo, g_ph, g_pl,
                    2 * D_MOD, D_MOD, m0, n0, sm);
    }
}

// ---------------------------------------------------------------------------
// P0[h,q,k] = (pos_q . pos_k) * SCALE + bias_table[k-q+1024, h]
// ---------------------------------------------------------------------------
#define PA_SMEM (4 * 18432 + 1024)

__global__ void __launch_bounds__(256) posattn_kernel(const float* __restrict__ bias_table) {
    extern __shared__ char sm[];
    const uint32_t sb = smem_u32(sm);
    const int tid = threadIdx.x, lane = tid & 31, wid = tid >> 5;
    const int wm = wid >> 2, wn = wid & 3;
    const int h = blockIdx.z, q0 = blockIdx.y * 128, k0 = blockIdx.x * 128;
    const int hc = h * 64;
    const int lj = lane >> 3, lr = lane & 7;

#pragma unroll
    for (int it = 0; it < 4; it++) {
        int e = tid + (it << 8);
        int r = e >> 3, c = e & 7;
        size_t qa = (size_t)(q0 + r) * 2048 + 1024 + hc + c * 8;
        size_t ka = (size_t)(k0 + r) * 2048 + hc + c * 8;
        uint32_t o = r * 144 + c * 16;
        cp_async16(sb + o, g_ph + qa);
        cp_async16(sb + 18432 + o, g_pl + qa);
        cp_async16(sb + 36864 + o, g_ph + ka);
        cp_async16(sb + 55296 + o, g_pl + ka);
    }
    {
        int rel = k0 - q0 + 897 + tid;
        rel = rel < 0 ? 0 : (rel > 2047 ? 2047 : rel);
        cp_async4(sb + 73728 + tid * 4, bias_table + rel * N_H + h);
    }
    CP_COMMIT();
    CP_WAIT(0);
    __syncthreads();

    float acc[4][4][4];
#pragma unroll
    for (int i = 0; i < 4; i++)
#pragma unroll
        for (int j = 0; j < 4; j++)
#pragma unroll
            for (int r = 0; r < 4; r++) acc[i][j][r] = 0.f;

#pragma unroll
    for (int kk = 0; kk < 4; kk++) {
        uint32_t ah[4][4], al[4][4];
#pragma unroll
        for (int tm = 0; tm < 4; tm++) {
            int m = wm * 64 + tm * 16 + (lj & 1) * 8 + lr;
            int k = kk * 16 + (lj >> 1) * 8;
            ldm_x4(ah[tm], sb + m * 144 + k * 2);
            ldm_x4(al[tm], sb + 18432 + m * 144 + k * 2);
        }
        uint32_t bh[2][4], bl[2][4];
#pragma unroll
        for (int tn = 0; tn < 2; tn++) {
            int n = wn * 32 + tn * 16 + (lj >> 1) * 8 + lr;
            int k = kk * 16 + (lj & 1) * 8;
            ldm_x4(bh[tn], sb + 36864 + n * 144 + k * 2);
            ldm_x4(bl[tn], sb + 55296 + n * 144 + k * 2);
        }
#pragma unroll
        for (int tm = 0; tm < 4; tm++)
#pragma unroll
            for (int t8 = 0; t8 < 4; t8++) {
                uint32_t bhr[2] = {bh[t8 >> 1][2 * (t8 & 1)], bh[t8 >> 1][2 * (t8 & 1) + 1]};
                uint32_t blr[2] = {bl[t8 >> 1][2 * (t8 & 1)], bl[t8 >> 1][2 * (t8 & 1) + 1]};
                mma_f16(acc[tm][t8], ah[tm], bhr);
                mma_f16(acc[tm][t8], ah[tm], blr);
                mma_f16(acc[tm][t8], al[tm], bhr);
            }
    }

    const float* bias_s = (const float*)(sm + 73728);
    float* P0b = g_P0 + ((size_t)h << 20);
#pragma unroll
    for (int tm = 0; tm < 4; tm++) {
        int q = wm * 64 + tm * 16 + (lane >> 2);
#pragma unroll
        for (int t8 = 0; t8 < 4; t8++) {
            int k = wn * 32 + t8 * 8 + 2 * (lane & 3);
            int idx = k - q + 127;
            float o0 = acc[tm][t8][0] * SCALE_F + bias_s[idx];
            float o1 = acc[tm][t8][1] * SCALE_F + bias_s[idx + 1];
            float o2 = acc[tm][t8][2] * SCALE_F + bias_s[idx - 8];
            float o3 = acc[tm][t8][3] * SCALE_F + bias_s[idx - 7];
            *(float2*)(P0b + (size_t)(q0 + q) * 1024 + k0 + k) = make_float2(o0, o1);
            *(float2*)(P0b + (size_t)(q0 + q + 8) * 1024 + k0 + k) = make_float2(o2, o3);
        }
    }
}

// ---------------------------------------------------------------------------
// Tensor-core flash attention (R10 best config): de=64 tok-only, P0+bias
// staged via cp.async into smem, occ 2. QK 3-pass, PV 1-pass.
// ---------------------------------------------------------------------------
#define KROW2 144
#define KB2 9216
#define P0ROW 272
#define STG (3 * KB2 + 64 * P0ROW)   // 45056
#define FL_SMEM (2 * STG)            // 90112

__device__ __forceinline__ void fl_prefetch_tile(uint32_t sb, int b, int h, int hc,
                                                 int q0, int k0, int s, int tid) {
    const uint32_t kb = sb + s * STG;
    const size_t rb = ((size_t)b * S_LEN + k0) * 3072;
#pragma unroll
    for (int it = 0; it < 4; it++) {
        int e = tid + (it << 7);
        int k = e >> 3, c = e & 7;
        size_t so = rb + (size_t)k * 3072 + hc + c * 8;
        uint32_t o = k * KROW2 + c * 16;
        cp_async16(kb + o, g_th + so);
        cp_async16(kb + KB2 + o, g_tl + so);
        size_t sv = rb + (size_t)k * 3072 + 2048 + hc + c * 8;
        cp_async16(kb + 2 * KB2 + o, g_th + sv);
    }
    const float* p0src = g_P0 + ((size_t)h << 20) + (size_t)q0 * 1024 + k0;
#pragma unroll
    for (int it = 0; it < 8; it++) {
        int e = tid + (it << 7);
        int r = e >> 4, c = e & 15;
        cp_async16(kb + 3 * KB2 + r * P0ROW + c * 16, p0src + (size_t)r * 1024 + c * 4);
    }
}

__global__ void __launch_bounds__(128, 2) flash_kernel(float* __restrict__ out) {
    extern __shared__ char sm[];
    const uint32_t sb = smem_u32(sm);
    const int tid = threadIdx.x, lane = tid & 31, wid = tid >> 5;
    const int lj = lane >> 3, lr = lane & 7;
    const int b = blockIdx.z, h = blockIdx.y, q0 = blockIdx.x * 64;
    const int hc = h * 64;
    const int m0w = wid * 16;

    {
        const size_t rb = ((size_t)b * S_LEN + q0) * 3072;
#pragma unroll
        for (int it = 0; it < 4; it++) {
            int e = tid + (it << 7);
            int q = e >> 3, c = e & 7;
            size_t so = rb + (size_t)q * 3072 + 1024 + hc + c * 8;
            cp_async16(sb + q * KROW2 + c * 16, g_th + so);
            cp_async16(sb + STG + q * KROW2 + c * 16, g_tl + so);
        }
        CP_COMMIT();
        CP_WAIT(0);
        __syncthreads();
    }
    uint32_t qh[4][4], qlo[4][4];
#pragma unroll
    for (int dk = 0; dk < 4; dk++) {
        uint32_t qa = sb + (m0w + (lj & 1) * 8 + lr) * KROW2 + (dk * 16 + (lj >> 1) * 8) * 2;
        ldm_x4(qh[dk], qa);
        ldm_x4(qlo[dk], qa + STG);
    }
    __syncthreads();

    fl_prefetch_tile(sb, b, h, hc, q0, 0, 0, tid);
    CP_COMMIT();

    float O[8][4];
#pragma unroll
    for (int i = 0; i < 8; i++)
#pragma unroll
        for (int j = 0; j < 4; j++) O[i][j] = 0.f;
    float m0 = -INFINITY, m1 = -INFINITY, l0 = 0.f, l1 = 0.f;

    const float LOG2E = 1.4426950408889634f;
    const int NT = S_LEN / 64;

    for (int kt = 0; kt < NT; kt++) {
        const int s = kt & 1;
        if (kt + 1 < NT) {
            fl_prefetch_tile(sb, b, h, hc, q0, (kt + 1) * 64, s ^ 1, tid);
            CP_COMMIT();
            CP_WAIT(1);
        } else {
            CP_WAIT(0);
        }
        __syncthreads();

        const uint32_t khb = sb + s * STG;
        const uint32_t vhb = khb + 2 * KB2;
        const char* p0s = sm + s * STG + 3 * KB2;

        float Sa[8][4];
#pragma unroll
        for (int i = 0; i < 8; i++)
#pragma unroll
            for (int j = 0; j < 4; j++) Sa[i][j] = 0.f;

#pragma unroll
        for (int dk = 0; dk < 4; dk++) {
#pragma unroll
            for (int ng = 0; ng < 4; ng++) {
                uint32_t bh[4], bl[4];
                uint32_t ka = khb + (ng * 16 + (lj >> 1) * 8 + lr) * KROW2 + (dk * 16 + (lj & 1) * 8) * 2;
                ldm_x4(bh, ka);
                ldm_x4(bl, ka + KB2);
                uint32_t b0[2] = {bh[0], bh[1]}, c0[2] = {bl[0], bl[1]};
                mma_f16(Sa[2 * ng], qh[dk], b0);
                mma_f16(Sa[2 * ng], qh[dk], c0);
                mma_f16(Sa[2 * ng], qlo[dk], b0);
                uint32_t b1[2] = {bh[2], bh[3]}, c1[2] = {bl[2], bl[3]};
                mma_f16(Sa[2 * ng + 1], qh[dk], b1);
                mma_f16(Sa[2 * ng + 1], qh[dk], c1);
                mma_f16(Sa[2 * ng + 1], qlo[dk], b1);
            }
        }

        const int qr = m0w + (lane >> 2);
        float mx0 = -INFINITY, mx1 = -INFINITY;
#pragma unroll
        for (int tt = 0; tt < 8; tt++) {
            int kl = 8 * tt + 2 * (lane & 3);
            float2 b0 = *(const float2*)(p0s + qr * P0ROW + kl * 4);
            float2 b1 = *(const float2*)(p0s + (qr + 8) * P0ROW + kl * 4);
            float s0 = Sa[tt][0] * SCALE_F + b0.x;
            float s1 = Sa[tt][1] * SCALE_F + b0.y;
            float s2 = Sa[tt][2] * SCALE_F + b1.x;
            float s3 = Sa[tt][3] * SCALE_F + b1.y;
            Sa[tt][0] = s0; Sa[tt][1] = s1; Sa[tt][2] = s2; Sa[tt][3] = s3;
            mx0 = fmaxf(mx0, fmaxf(s0, s1));
            mx1 = fmaxf(mx1, fmaxf(s2, s3));
        }
        mx0 = fmaxf(mx0, __shfl_xor_sync(0xffffffffu, mx0, 1));
        mx0 = fmaxf(mx0, __shfl_xor_sync(0xffffffffu, mx0, 2));
        mx1 = fmaxf(mx1, __shfl_xor_sync(0xffffffffu, mx1, 1));
        mx1 = fmaxf(mx1, __shfl_xor_sync(0xffffffffu, mx1, 2));
        float mn0 = fmaxf(m0, mx0), mn1 = fmaxf(m1, mx1);
        float a0 = exp2f((m0 - mn0) * LOG2E), a1 = exp2f((m1 - mn1) * LOG2E);
        m0 = mn0; m1 = mn1;

        uint32_t ph0[8], ph1[8];
        float r0 = 0.f, r1 = 0.f;
#pragma unroll
        for (int tt = 0; tt < 8; tt++) {
            float p0 = exp2f((Sa[tt][0] - m0) * LOG2E);
            float p1 = exp2f((Sa[tt][1] - m0) * LOG2E);
            float p2 = exp2f((Sa[tt][2] - m1) * LOG2E);
            float p3 = exp2f((Sa[tt][3] - m1) * LOG2E);
            r0 += p0 + p1; r1 += p2 + p3;
            ph0[tt] = h2u(__floats2half2_rn(p0, p1));
            ph1[tt] = h2u(__floats2half2_rn(p2, p3));
        }
        r0 += __shfl_xor_sync(0xffffffffu, r0, 1);
        r0 += __shfl_xor_sync(0xffffffffu, r0, 2);
        r1 += __shfl_xor_sync(0xffffffffu, r1, 1);
        r1 += __shfl_xor_sync(0xffffffffu, r1, 2);
        l0 = l0 * a0 + r0;
        l1 = l1 * a1 + r1;
#pragma unroll
        for (int dt = 0; dt < 8; dt++) {
            O[dt][0] *= a0; O[dt][1] *= a0; O[dt][2] *= a1; O[dt][3] *= a1;
        }

#pragma unroll
        for (int ck = 0; ck < 4; ck++) {
            uint32_t Ah[4] = {ph0[2 * ck], ph1[2 * ck], ph0[2 * ck + 1], ph1[2 * ck + 1]};
#pragma unroll
            for (int dg = 0; dg < 4; dg++) {
                uint32_t vh[4];
                uint32_t va = vhb + (ck * 16 + (lj & 1) * 8 + lr) * KROW2 + (dg * 16 + (lj >> 1) * 8) * 2;
                ldm_x4t(vh, va);
                uint32_t v0[2] = {vh[0], vh[1]};
                mma_f16(O[2 * dg], Ah, v0);
                uint32_t v1[2] = {vh[2], vh[3]};
                mma_f16(O[2 * dg + 1], Ah, v1);
            }
        }
        __syncthreads();
    }

    float inv0 = 1.f / l0, inv1 = 1.f / l1;
    size_t row = (size_t)b * S_LEN + q0 + m0w + (lane >> 2);
#pragma unroll
    for (int dt = 0; dt < 8; dt++) {
        int n = hc + dt * 8 + 2 * (lane & 3);
        *(float2*)(out + row * D_MOD + n) = make_float2(O[dt][0] * inv0, O[dt][1] * inv0);
        *(float2*)(out + (row + 8) * D_MOD + n) = make_float2(O[dt][2] * inv1, O[dt][3] * inv1);
    }
}

// ---------------------------------------------------------------------------
// Launch (single stream — block-range fusion)
// ---------------------------------------------------------------------------
extern "C" void kernel_launch(void* const* d_in, const int* in_sizes, int n_in,
                              void* d_out, int out_size) {
    const float* x          = (const float*)d_in[0];
    const float* gamma      = (const float*)d_in[1];
    const float* beta       = (const float*)d_in[2];
    const float* w_pos      = (const float*)d_in[3];
    const float* w_tok      = (const float*)d_in[4];
    const float* bias_table = (const float*)d_in[5];
    float* out = (float*)d_out;

    cudaFuncSetAttribute(gemm_merged, cudaFuncAttributeMaxDynamicSharedMemorySize, GEMM_SMEM);
    cudaFuncSetAttribute(posattn_kernel, cudaFuncAttributeMaxDynamicSharedMemorySize, PA_SMEM);
    cudaFuncSetAttribute(flash_kernel, cudaFuncAttributeMaxDynamicSharedMemorySize, FL_SMEM);

    // fused elementwise: pe + w_pos split + w_tok split + layernorm
    prep_kernel<<<10240, 256>>>(w_pos, w_tok, x, gamma, beta);
    // merged GEMMs: tok 128x128 (768) + pos 64x128 (256) — tail-packed
    gemm_merged<<<1024, 256, GEMM_SMEM>>>();
    // P0 = pos_attn*SCALE + bias (batch-independent)
    posattn_kernel<<<dim3(8, 8, 16), 256, PA_SMEM>>>(bias_table);
    // flash attention (R10 config: de=64, P0 smem-staged, occ 2)
    flash_kernel<<<dim3(S_LEN / 64, N_H, B_SZ), 128, FL_SMEM>>>(out);
}

// round 15
// speedup vs baseline: 1.0534x; 1.0427x over previous
#include <cuda_runtime.h>
#include <cuda_fp16.h>
#include <math.h>
#include <stdint.h>

#define S_LEN 1024
#define D_MOD 1024
#define B_SZ 4
#define N_H 16
#define MAXLEN 1024

// ---------------------------------------------------------------------------
// Scratch (device globals — no allocations allowed)
// ---------------------------------------------------------------------------
__device__ __half g_pe_hi[S_LEN * D_MOD],        g_pe_lo[S_LEN * D_MOD];
__device__ __half g_wpos_hi[2 * D_MOD * D_MOD],  g_wpos_lo[2 * D_MOD * D_MOD];
__device__ __half g_xn_hi[B_SZ * S_LEN * D_MOD], g_xn_lo[B_SZ * S_LEN * D_MOD];
__device__ __half g_wtok_hi[3 * D_MOD * D_MOD],  g_wtok_lo[3 * D_MOD * D_MOD];
__device__ __half g_ph[S_LEN * 2 * D_MOD], g_pl[S_LEN * 2 * D_MOD];                      // pos
__device__ __half g_th[(size_t)B_SZ * S_LEN * 3 * D_MOD], g_tl[(size_t)B_SZ * S_LEN * 3 * D_MOD]; // tok
__device__ float  g_P0[(size_t)N_H * S_LEN * S_LEN];      // pos_attn*SCALE + bias, 67MB

// ---------------------------------------------------------------------------
// helpers
// ---------------------------------------------------------------------------
__device__ __forceinline__ uint32_t smem_u32(const void* p) {
    uint32_t a;
    asm("{ .reg .u64 t; cvta.to.shared.u64 t, %1; cvt.u32.u64 %0, t; }" : "=r"(a) : "l"(p));
    return a;
}
__device__ __forceinline__ void cp_async16(uint32_t dst, const void* src) {
    asm volatile("cp.async.cg.shared.global [%0], [%1], 16;" :: "r"(dst), "l"(src) : "memory");
}
__device__ __forceinline__ void cp_async4(uint32_t dst, const void* src) {
    asm volatile("cp.async.ca.shared.global [%0], [%1], 4;" :: "r"(dst), "l"(src) : "memory");
}
#define CP_COMMIT() asm volatile("cp.async.commit_group;" ::: "memory")
#define CP_WAIT(n)  asm volatile("cp.async.wait_group %0;" :: "n"(n) : "memory")

__device__ __forceinline__ void ldm_x4(uint32_t* r, uint32_t addr) {
    asm volatile("ldmatrix.sync.aligned.m8n8.x4.shared.b16 {%0,%1,%2,%3}, [%4];"
                 : "=r"(r[0]), "=r"(r[1]), "=r"(r[2]), "=r"(r[3]) : "r"(addr));
}
__device__ __forceinline__ void ldm_x4t(uint32_t* r, uint32_t addr) {
    asm volatile("ldmatrix.sync.aligned.m8n8.x4.trans.shared.b16 {%0,%1,%2,%3}, [%4];"
                 : "=r"(r[0]), "=r"(r[1]), "=r"(r[2]), "=r"(r[3]) : "r"(addr));
}
__device__ __forceinline__ void mma_f16(float* c, const uint32_t* a, const uint32_t* b) {
    asm volatile("mma.sync.aligned.m16n8k16.row.col.f32.f16.f16.f32 "
                 "{%0,%1,%2,%3}, {%4,%5,%6,%7}, {%8,%9}, {%0,%1,%2,%3};"
                 : "+f"(c[0]), "+f"(c[1]), "+f"(c[2]), "+f"(c[3])
                 : "r"(a[0]), "r"(a[1]), "r"(a[2]), "r"(a[3]), "r"(b[0]), "r"(b[1]));
}
__device__ __forceinline__ uint32_t h2u(__half2 h) { return *reinterpret_cast<uint32_t*>(&h); }

#define SCALE_F 11.313708498984761f   // sqrt(2*dh)

// ---------------------------------------------------------------------------
// Fused prep: pe + w_pos split + w_tok split + layernorm (all independent)
// blocks: [0,1024) pe | [1024,3072) w_pos | [3072,6144) w_tok | [6144,10240) ln
// ---------------------------------------------------------------------------
__device__ __forceinline__ void split4_body(const float4* __restrict__ src,
                                            uint32_t* __restrict__ hi,
                                            uint32_t* __restrict__ lo, int i) {
    float4 v = src[i];
    __half2 h0 = __floats2half2_rn(v.x, v.y);
    __half2 h1 = __floats2half2_rn(v.z, v.w);
    __half2 l0 = __floats2half2_rn(v.x - __low2float(h0), v.y - __high2float(h0));
    __half2 l1 = __floats2half2_rn(v.z - __low2float(h1), v.w - __high2float(h1));
    hi[2 * i] = h2u(h0); hi[2 * i + 1] = h2u(h1);
    lo[2 * i] = h2u(l0); lo[2 * i + 1] = h2u(l1);
}

__global__ void __launch_bounds__(256) prep_kernel(const float* __restrict__ w_pos,
                                                   const float* __restrict__ w_tok,
                                                   const float* __restrict__ x,
                                                   const float* __restrict__ gamma,
                                                   const float* __restrict__ beta) {
    const int bx = blockIdx.x, t = threadIdx.x;
    if (bx < 1024) {                     // sinusoidal PE -> fp16 hi/lo
        int s = bx;
        for (int d = t; d < D_MOD; d += 256) {
            int i = d >> 1;
            float div = expf((float)(2 * i) * (-9.210340371976184f / (float)D_MOD));
            float ang = (float)s * div;
            float v = (d & 1) ? cosf(ang) : sinf(ang);
            __half h = __float2half_rn(v);
            g_pe_hi[s * D_MOD + d] = h;
            g_pe_lo[s * D_MOD + d] = __float2half_rn(v - __half2float(h));
        }
    } else if (bx < 3072) {              // w_pos split
        split4_body((const float4*)w_pos, (uint32_t*)g_wpos_hi, (uint32_t*)g_wpos_lo,
                    (bx - 1024) * 256 + t);
    } else if (bx < 6144) {              // w_tok split
        split4_body((const float4*)w_tok, (uint32_t*)g_wtok_hi, (uint32_t*)g_wtok_lo,
                    (bx - 3072) * 256 + t);
    } else {                             // layernorm row
        const int row = bx - 6144;
        const float* xr = x + (size_t)row * D_MOD;
        const int lane = t & 31, wid = t >> 5;
        __shared__ float red[8];

        float v[4];
        float s = 0.f;
#pragma unroll
        for (int i = 0; i < 4; i++) { v[i] = xr[t + i * 256]; s += v[i]; }
#pragma unroll
        for (int o = 16; o > 0; o >>= 1) s += __shfl_xor_sync(0xffffffffu, s, o);
        if (lane == 0) red[wid] = s;
        __syncthreads();
        float tot = 0.f;
#pragma unroll
        for (int i = 0; i < 8; i++) tot += red[i];
        float mean = tot * (1.f / 1024.f);

        float sq = 0.f;
#pragma unroll
        for (int i = 0; i < 4; i++) { float d = v[i] - mean; sq += d * d; }
#pragma unroll
        for (int o = 16; o > 0; o >>= 1) sq += __shfl_xor_sync(0xffffffffu, sq, o);
        __syncthreads();
        if (lane == 0) red[wid] = sq;
        __syncthreads();
        float tot2 = 0.f;
#pragma unroll
        for (int i = 0; i < 8; i++) tot2 += red[i];
        float rstd = rsqrtf(tot2 * (1.f / 1024.f) + 1e-5f);

#pragma unroll
        for (int i = 0; i < 4; i++) {
            int c = t + i * 256;
            float y = (v[i] - mean) * rstd * gamma[c] + beta[c];
            __half h = __float2half_rn(y);
            g_xn_hi[(size_t)row * D_MOD + c] = h;
            g_xn_lo[(size_t)row * D_MOD + c] = __float2half_rn(y - __half2float(h));
        }
    }
}

// ---------------------------------------------------------------------------
// mma.sync fp16x2-split NT GEMM body (R10-proven), forced occupancy 2
// ---------------------------------------------------------------------------
#define OPBUF 10240
#define GEMM_SMEM (8 * OPBUF)

__device__ __forceinline__ void gemm_body(
    const __half* __restrict__ Ahi, const __half* __restrict__ Alo,
    const __half* __restrict__ Bhi, const __half* __restrict__ Blo,
    __half* __restrict__ Chi, __half* __restrict__ Clo,
    int N, int K, int m0, int n0, bool full, char* sm)
{
    const uint32_t sb = smem_u32(sm);
    const int tid = threadIdx.x;
    const int lane = tid & 31, wid = tid >> 5;
    const int wm = wid >> 2, wn = wid & 3;

    float acc[4][4][4];
#pragma unroll
    for (int i = 0; i < 4; i++)
#pragma unroll
        for (int j = 0; j < 4; j++)
#pragma unroll
            for (int r = 0; r < 4; r++) acc[i][j][r] = 0.f;

    const __half* srcs[4] = {Ahi, Alo, Bhi, Blo};
    const int rows0[4] = {m0, m0, n0, n0};
    const int NCH = K >> 5;
    const int lj = lane >> 3, lr = lane & 7;

#pragma unroll
    for (int op = 0; op < 4; op++) {
        if (op == 1 && !full) continue;
#pragma unroll
        for (int it = 0; it < 2; it++) {
            int e = tid + (it << 8);
            int r = e >> 2, cs = e & 3;
            cp_async16(sb + op * OPBUF + r * 80 + cs * 16,
                       srcs[op] + (size_t)(rows0[op] + r) * K + (cs << 3));
        }
    }
    CP_COMMIT();

    for (int i = 0; i < NCH; i++) {
        const int s = i & 1;
        if (i + 1 < NCH) {
            const int s2 = s ^ 1, k0 = (i + 1) << 5;
#pragma unroll
            for (int op = 0; op < 4; op++) {
                if (op == 1 && !full) continue;
#pragma unroll
                for (int it = 0; it < 2; it++) {
                    int e = tid + (it << 8);
                    int r = e >> 2, cs = e & 3;
                    cp_async16(sb + (s2 * 4 + op) * OPBUF + r * 80 + cs * 16,
                               srcs[op] + (size_t)(rows0[op] + r) * K + k0 + (cs << 3));
                }
            }
            CP_COMMIT();
            CP_WAIT(1);
        } else {
            CP_WAIT(0);
        }
        __syncthreads();

        const uint32_t ah_b = sb + (s * 4 + 0) * OPBUF;
        const uint32_t al_b = sb + (s * 4 + 1) * OPBUF;
        const uint32_t bh_b = sb + (s * 4 + 2) * OPBUF;
        const uint32_t bl_b = sb + (s * 4 + 3) * OPBUF;

#pragma unroll
        for (int kk = 0; kk < 32; kk += 16) {
            uint32_t ah[4][4], al[4][4];
#pragma unroll
            for (int tm = 0; tm < 4; tm++) {
                int m = wm * 64 + tm * 16 + (lj & 1) * 8 + lr;
                int k = kk + (lj >> 1) * 8;
                ldm_x4(ah[tm], ah_b + m * 80 + k * 2);
                if (full) ldm_x4(al[tm], al_b + m * 80 + k * 2);
            }
            uint32_t bh[2][4], bl[2][4];
#pragma unroll
            for (int tn = 0; tn < 2; tn++) {
                int n = wn * 32 + tn * 16 + (lj >> 1) * 8 + lr;
                int k = kk + (lj & 1) * 8;
                ldm_x4(bh[tn], bh_b + n * 80 + k * 2);
                ldm_x4(bl[tn], bl_b + n * 80 + k * 2);
            }
#pragma unroll
            for (int tm = 0; tm < 4; tm++)
#pragma unroll
                for (int t8 = 0; t8 < 4; t8++) {
                    uint32_t bhr[2] = {bh[t8 >> 1][2 * (t8 & 1)], bh[t8 >> 1][2 * (t8 & 1) + 1]};
                    uint32_t blr[2] = {bl[t8 >> 1][2 * (t8 & 1)], bl[t8 >> 1][2 * (t8 & 1) + 1]};
                    mma_f16(acc[tm][t8], ah[tm], bhr);
                    mma_f16(acc[tm][t8], ah[tm], blr);
                    if (full) mma_f16(acc[tm][t8], al[tm], bhr);
                }
        }
        __syncthreads();
    }

#pragma unroll
    for (int tm = 0; tm < 4; tm++) {
        int m = m0 + wm * 64 + tm * 16 + (lane >> 2);
#pragma unroll
        for (int t8 = 0; t8 < 4; t8++) {
            int n = n0 + wn * 32 + t8 * 8 + 2 * (lane & 3);
            float v0 = acc[tm][t8][0], v1 = acc[tm][t8][1];
            float v2 = acc[tm][t8][2], v3 = acc[tm][t8][3];
            __half2 h01 = __floats2half2_rn(v0, v1);
            __half2 h23 = __floats2half2_rn(v2, v3);
            *(__half2*)(Chi + (size_t)m * N + n) = h01;
            *(__half2*)(Chi + (size_t)(m + 8) * N + n) = h23;
            if (full) {
                __half2 l01 = __floats2half2_rn(v0 - __low2float(h01), v1 - __high2float(h01));
                __half2 l23 = __floats2half2_rn(v2 - __low2float(h23), v3 - __high2float(h23));
                *(__half2*)(Clo + (size_t)m * N + n) = l01;
                *(__half2*)(Clo + (size_t)(m + 8) * N + n) = l23;
            }
        }
    }
}

// merged launch: blocks [0,768) = tok (24 x 32), blocks [768,896) = pos (16 x 8)
// __launch_bounds__(256, 2): cap regs at 128 (currently 123 -> no spill) and
// guarantee 2 CTAs/SM so one CTA's MMAs cover the other's pipeline bubbles.
__global__ void __launch_bounds__(256, 2) gemm_merged() {
    extern __shared__ char sm[];
    int bx = blockIdx.x;
    if (bx < 768) {
        int n0 = (bx % 24) * 128, m0 = (bx / 24) * 128;
        gemm_body(g_xn_hi, g_xn_lo, g_wtok_hi, g_wtok_lo, g_th, g_tl,
                  3 * D_MOD, D_MOD, m0, n0, n0 < 2 * D_MOD, sm);
    } else {
        int bp = bx - 768;
        int n0 = (bp % 16) * 128, m0 = (bp / 16) * 128;
        gemm_body(g_pe_hi, g_pe_lo, g_wpos_hi, g_wpos_lo, g_ph, g_pl,
                  2 * D_MOD, D_MOD, m0, n0, true, sm);
    }
}

// ---------------------------------------------------------------------------
// P0[h,q,k] = (pos_q . pos_k) * SCALE + bias_table[k-q+1024, h]
// ---------------------------------------------------------------------------
#define PA_SMEM (4 * 18432 + 1024)

__global__ void __launch_bounds__(256) posattn_kernel(const float* __restrict__ bias_table) {
    extern __shared__ char sm[];
    const uint32_t sb = smem_u32(sm);
    const int tid = threadIdx.x, lane = tid & 31, wid = tid >> 5;
    const int wm = wid >> 2, wn = wid & 3;
    const int h = blockIdx.z, q0 = blockIdx.y * 128, k0 = blockIdx.x * 128;
    const int hc = h * 64;
    const int lj = lane >> 3, lr = lane & 7;

#pragma unroll
    for (int it = 0; it < 4; it++) {
        int e = tid + (it << 8);
        int r = e >> 3, c = e & 7;
        size_t qa = (size_t)(q0 + r) * 2048 + 1024 + hc + c * 8;
        size_t ka = (size_t)(k0 + r) * 2048 + hc + c * 8;
        uint32_t o = r * 144 + c * 16;
        cp_async16(sb + o, g_ph + qa);
        cp_async16(sb + 18432 + o, g_pl + qa);
        cp_async16(sb + 36864 + o, g_ph + ka);
        cp_async16(sb + 55296 + o, g_pl + ka);
    }
    {
        int rel = k0 - q0 + 897 + tid;
        rel = rel < 0 ? 0 : (rel > 2047 ? 2047 : rel);
        cp_async4(sb + 73728 + tid * 4, bias_table + rel * N_H + h);
    }
    CP_COMMIT();
    CP_WAIT(0);
    __syncthreads();

    float acc[4][4][4];
#pragma unroll
    for (int i = 0; i < 4; i++)
#pragma unroll
        for (int j = 0; j < 4; j++)
#pragma unroll
            for (int r = 0; r < 4; r++) acc[i][j][r] = 0.f;

#pragma unroll
    for (int kk = 0; kk < 4; kk++) {
        uint32_t ah[4][4], al[4][4];
#pragma unroll
        for (int tm = 0; tm < 4; tm++) {
            int m = wm * 64 + tm * 16 + (lj & 1) * 8 + lr;
            int k = kk * 16 + (lj >> 1) * 8;
            ldm_x4(ah[tm], sb + m * 144 + k * 2);
            ldm_x4(al[tm], sb + 18432 + m * 144 + k * 2);
        }
        uint32_t bh[2][4], bl[2][4];
#pragma unroll
        for (int tn = 0; tn < 2; tn++) {
            int n = wn * 32 + tn * 16 + (lj >> 1) * 8 + lr;
            int k = kk * 16 + (lj & 1) * 8;
            ldm_x4(bh[tn], sb + 36864 + n * 144 + k * 2);
            ldm_x4(bl[tn], sb + 55296 + n * 144 + k * 2);
        }
#pragma unroll
        for (int tm = 0; tm < 4; tm++)
#pragma unroll
            for (int t8 = 0; t8 < 4; t8++) {
                uint32_t bhr[2] = {bh[t8 >> 1][2 * (t8 & 1)], bh[t8 >> 1][2 * (t8 & 1) + 1]};
                uint32_t blr[2] = {bl[t8 >> 1][2 * (t8 & 1)], bl[t8 >> 1][2 * (t8 & 1) + 1]};
                mma_f16(acc[tm][t8], ah[tm], bhr);
                mma_f16(acc[tm][t8], ah[tm], blr);
                mma_f16(acc[tm][t8], al[tm], bhr);
            }
    }

    const float* bias_s = (const float*)(sm + 73728);
    float* P0b = g_P0 + ((size_t)h << 20);
#pragma unroll
    for (int tm = 0; tm < 4; tm++) {
        int q = wm * 64 + tm * 16 + (lane >> 2);
#pragma unroll
        for (int t8 = 0; t8 < 4; t8++) {
            int k = wn * 32 + t8 * 8 + 2 * (lane & 3);
            int idx = k - q + 127;
            float o0 = acc[tm][t8][0] * SCALE_F + bias_s[idx];
            float o1 = acc[tm][t8][1] * SCALE_F + bias_s[idx + 1];
            float o2 = acc[tm][t8][2] * SCALE_F + bias_s[idx - 8];
            float o3 = acc[tm][t8][3] * SCALE_F + bias_s[idx - 7];
            *(float2*)(P0b + (size_t)(q0 + q) * 1024 + k0 + k) = make_float2(o0, o1);
            *(float2*)(P0b + (size_t)(q0 + q + 8) * 1024 + k0 + k) = make_float2(o2, o3);
        }
    }
}

// ---------------------------------------------------------------------------
// Tensor-core flash attention (R10 best config): de=64 tok-only, P0+bias
// staged via cp.async into smem, occ 2. QK 3-pass, PV 1-pass.
// ---------------------------------------------------------------------------
#define KROW2 144
#define KB2 9216
#define P0ROW 272
#define STG (3 * KB2 + 64 * P0ROW)   // 45056
#define FL_SMEM (2 * STG)            // 90112

__device__ __forceinline__ void fl_prefetch_tile(uint32_t sb, int b, int h, int hc,
                                                 int q0, int k0, int s, int tid) {
    const uint32_t kb = sb + s * STG;
    const size_t rb = ((size_t)b * S_LEN + k0) * 3072;
#pragma unroll
    for (int it = 0; it < 4; it++) {
        int e = tid + (it << 7);
        int k = e >> 3, c = e & 7;
        size_t so = rb + (size_t)k * 3072 + hc + c * 8;
        uint32_t o = k * KROW2 + c * 16;
        cp_async16(kb + o, g_th + so);
        cp_async16(kb + KB2 + o, g_tl + so);
        size_t sv = rb + (size_t)k * 3072 + 2048 + hc + c * 8;
        cp_async16(kb + 2 * KB2 + o, g_th + sv);
    }
    const float* p0src = g_P0 + ((size_t)h << 20) + (size_t)q0 * 1024 + k0;
#pragma unroll
    for (int it = 0; it < 8; it++) {
        int e = tid + (it << 7);
        int r = e >> 4, c = e & 15;
        cp_async16(kb + 3 * KB2 + r * P0ROW + c * 16, p0src + (size_t)r * 1024 + c * 4);
    }
}

__global__ void __launch_bounds__(128, 2) flash_kernel(float* __restrict__ out) {
    extern __shared__ char sm[];
    const uint32_t sb = smem_u32(sm);
    const int tid = threadIdx.x, lane = tid & 31, wid = tid >> 5;
    const int lj = lane >> 3, lr = lane & 7;
    const int b = blockIdx.z, h = blockIdx.y, q0 = blockIdx.x * 64;
    const int hc = h * 64;
    const int m0w = wid * 16;

    {
        const size_t rb = ((size_t)b * S_LEN + q0) * 3072;
#pragma unroll
        for (int it = 0; it < 4; it++) {
            int e = tid + (it << 7);
            int q = e >> 3, c = e & 7;
            size_t so = rb + (size_t)q * 3072 + 1024 + hc + c * 8;
            cp_async16(sb + q * KROW2 + c * 16, g_th + so);
            cp_async16(sb + STG + q * KROW2 + c * 16, g_tl + so);
        }
        CP_COMMIT();
        CP_WAIT(0);
        __syncthreads();
    }
    uint32_t qh[4][4], qlo[4][4];
#pragma unroll
    for (int dk = 0; dk < 4; dk++) {
        uint32_t qa = sb + (m0w + (lj & 1) * 8 + lr) * KROW2 + (dk * 16 + (lj >> 1) * 8) * 2;
        ldm_x4(qh[dk], qa);
        ldm_x4(qlo[dk], qa + STG);
    }
    __syncthreads();

    fl_prefetch_tile(sb, b, h, hc, q0, 0, 0, tid);
    CP_COMMIT();

    float O[8][4];
#pragma unroll
    for (int i = 0; i < 8; i++)
#pragma unroll
        for (int j = 0; j < 4; j++) O[i][j] = 0.f;
    float m0 = -INFINITY, m1 = -INFINITY, l0 = 0.f, l1 = 0.f;

    const float LOG2E = 1.4426950408889634f;
    const int NT = S_LEN / 64;

    for (int kt = 0; kt < NT; kt++) {
        const int s = kt & 1;
        if (kt + 1 < NT) {
            fl_prefetch_tile(sb, b, h, hc, q0, (kt + 1) * 64, s ^ 1, tid);
            CP_COMMIT();
            CP_WAIT(1);
        } else {
            CP_WAIT(0);
        }
        __syncthreads();

        const uint32_t khb = sb + s * STG;
        const uint32_t vhb = khb + 2 * KB2;
        const char* p0s = sm + s * STG + 3 * KB2;

        float Sa[8][4];
#pragma unroll
        for (int i = 0; i < 8; i++)
#pragma unroll
            for (int j = 0; j < 4; j++) Sa[i][j] = 0.f;

#pragma unroll
        for (int dk = 0; dk < 4; dk++) {
#pragma unroll
            for (int ng = 0; ng < 4; ng++) {
                uint32_t bh[4], bl[4];
                uint32_t ka = khb + (ng * 16 + (lj >> 1) * 8 + lr) * KROW2 + (dk * 16 + (lj & 1) * 8) * 2;
                ldm_x4(bh, ka);
                ldm_x4(bl, ka + KB2);
                uint32_t b0[2] = {bh[0], bh[1]}, c0[2] = {bl[0], bl[1]};
                mma_f16(Sa[2 * ng], qh[dk], b0);
                mma_f16(Sa[2 * ng], qh[dk], c0);
                mma_f16(Sa[2 * ng], qlo[dk], b0);
                uint32_t b1[2] = {bh[2], bh[3]}, c1[2] = {bl[2], bl[3]};
                mma_f16(Sa[2 * ng + 1], qh[dk], b1);
                mma_f16(Sa[2 * ng + 1], qh[dk], c1);
                mma_f16(Sa[2 * ng + 1], qlo[dk], b1);
            }
        }

        const int qr = m0w + (lane >> 2);
        float mx0 = -INFINITY, mx1 = -INFINITY;
#pragma unroll
        for (int tt = 0; tt < 8; tt++) {
            int kl = 8 * tt + 2 * (lane & 3);
            float2 b0 = *(const float2*)(p0s + qr * P0ROW + kl * 4);
            float2 b1 = *(const float2*)(p0s + (qr + 8) * P0ROW + kl * 4);
            float s0 = Sa[tt][0] * SCALE_F + b0.x;
            float s1 = Sa[tt][1] * SCALE_F + b0.y;
            float s2 = Sa[tt][2] * SCALE_F + b1.x;
            float s3 = Sa[tt][3] * SCALE_F + b1.y;
            Sa[tt][0] = s0; Sa[tt][1] = s1; Sa[tt][2] = s2; Sa[tt][3] = s3;
            mx0 = fmaxf(mx0, fmaxf(s0, s1));
            mx1 = fmaxf(mx1, fmaxf(s2, s3));
        }
        mx0 = fmaxf(mx0, __shfl_xor_sync(0xffffffffu, mx0, 1));
        mx0 = fmaxf(mx0, __shfl_xor_sync(0xffffffffu, mx0, 2));
        mx1 = fmaxf(mx1, __shfl_xor_sync(0xffffffffu, mx1, 1));
        mx1 = fmaxf(mx1, __shfl_xor_sync(0xffffffffu, mx1, 2));
        float mn0 = fmaxf(m0, mx0), mn1 = fmaxf(m1, mx1);
        float a0 = exp2f((m0 - mn0) * LOG2E), a1 = exp2f((m1 - mn1) * LOG2E);
        m0 = mn0; m1 = mn1;

        uint32_t ph0[8], ph1[8];
        float r0 = 0.f, r1 = 0.f;
#pragma unroll
        for (int tt = 0; tt < 8; tt++) {
            float p0 = exp2f((Sa[tt][0] - m0) * LOG2E);
            float p1 = exp2f((Sa[tt][1] - m0) * LOG2E);
            float p2 = exp2f((Sa[tt][2] - m1) * LOG2E);
            float p3 = exp2f((Sa[tt][3] - m1) * LOG2E);
            r0 += p0 + p1; r1 += p2 + p3;
            ph0[tt] = h2u(__floats2half2_rn(p0, p1));
            ph1[tt] = h2u(__floats2half2_rn(p2, p3));
        }
        r0 += __shfl_xor_sync(0xffffffffu, r0, 1);
        r0 += __shfl_xor_sync(0xffffffffu, r0, 2);
        r1 += __shfl_xor_sync(0xffffffffu, r1, 1);
        r1 += __shfl_xor_sync(0xffffffffu, r1, 2);
        l0 = l0 * a0 + r0;
        l1 = l1 * a1 + r1;
#pragma unroll
        for (int dt = 0; dt < 8; dt++) {
            O[dt][0] *= a0; O[dt][1] *= a0; O[dt][2] *= a1; O[dt][3] *= a1;
        }

#pragma unroll
        for (int ck = 0; ck < 4; ck++) {
            uint32_t Ah[4] = {ph0[2 * ck], ph1[2 * ck], ph0[2 * ck + 1], ph1[2 * ck + 1]};
#pragma unroll
            for (int dg = 0; dg < 4; dg++) {
                uint32_t vh[4];
                uint32_t va = vhb + (ck * 16 + (lj & 1) * 8 + lr) * KROW2 + (dg * 16 + (lj >> 1) * 8) * 2;
                ldm_x4t(vh, va);
                uint32_t v0[2] = {vh[0], vh[1]};
                mma_f16(O[2 * dg], Ah, v0);
                uint32_t v1[2] = {vh[2], vh[3]};
                mma_f16(O[2 * dg + 1], Ah, v1);
            }
        }
        __syncthreads();
    }

    float inv0 = 1.f / l0, inv1 = 1.f / l1;
    size_t row = (size_t)b * S_LEN + q0 + m0w + (lane >> 2);
#pragma unroll
    for (int dt = 0; dt < 8; dt++) {
        int n = hc + dt * 8 + 2 * (lane & 3);
        *(float2*)(out + row * D_MOD + n) = make_float2(O[dt][0] * inv0, O[dt][1] * inv0);
        *(float2*)(out + (row + 8) * D_MOD + n) = make_float2(O[dt][2] * inv1, O[dt][3] * inv1);
    }
}

// ---------------------------------------------------------------------------
// Launch (single stream — block-range fusion)
// ---------------------------------------------------------------------------
extern "C" void kernel_launch(void* const* d_in, const int* in_sizes, int n_in,
                              void* d_out, int out_size) {
    const float* x          = (const float*)d_in[0];
    const float* gamma      = (const float*)d_in[1];
    const float* beta       = (const float*)d_in[2];
    const float* w_pos      = (const float*)d_in[3];
    const float* w_tok      = (const float*)d_in[4];
    const float* bias_table = (const float*)d_in[5];
    float* out = (float*)d_out;

    cudaFuncSetAttribute(gemm_merged, cudaFuncAttributeMaxDynamicSharedMemorySize, GEMM_SMEM);
    cudaFuncSetAttribute(posattn_kernel, cudaFuncAttributeMaxDynamicSharedMemorySize, PA_SMEM);
    cudaFuncSetAttribute(flash_kernel, cudaFuncAttributeMaxDynamicSharedMemorySize, FL_SMEM);

    // fused elementwise: pe + w_pos split + w_tok split + layernorm
    prep_kernel<<<10240, 256>>>(w_pos, w_tok, x, gamma, beta);
    // merged GEMMs: tok (768 blocks) + pos (128 blocks), forced occ 2
    gemm_merged<<<896, 256, GEMM_SMEM>>>();
    // P0 = pos_attn*SCALE + bias (batch-independent)
    posattn_kernel<<<dim3(8, 8, 16), 256, PA_SMEM>>>(bias_table);
    // flash attention (R10 config: de=64, P0 smem-staged, occ 2)
    flash_kernel<<<dim3(S_LEN / 64, N_H, B_SZ), 128, FL_SMEM>>>(out);
}

// round 16
// speedup vs baseline: 1.0985x; 1.0429x over previous
#include <cuda_runtime.h>
#include <cuda_fp16.h>
#include <math.h>
#include <stdint.h>

#define S_LEN 1024
#define D_MOD 1024
#define B_SZ 4
#define N_H 16
#define MAXLEN 1024

// ---------------------------------------------------------------------------
// Scratch (device globals — no allocations allowed)
// ---------------------------------------------------------------------------
__device__ __half g_pe_hi[S_LEN * D_MOD],        g_pe_lo[S_LEN * D_MOD];
__device__ __half g_wpos_hi[2 * D_MOD * D_MOD],  g_wpos_lo[2 * D_MOD * D_MOD];
__device__ __half g_xn_hi[B_SZ * S_LEN * D_MOD], g_xn_lo[B_SZ * S_LEN * D_MOD];
__device__ __half g_wtok_hi[3 * D_MOD * D_MOD],  g_wtok_lo[3 * D_MOD * D_MOD];
__device__ __half g_ph[S_LEN * 2 * D_MOD], g_pl[S_LEN * 2 * D_MOD];                      // pos
__device__ __half g_th[(size_t)B_SZ * S_LEN * 3 * D_MOD], g_tl[(size_t)B_SZ * S_LEN * 3 * D_MOD]; // tok
__device__ float  g_P0[(size_t)N_H * S_LEN * S_LEN];      // pos_attn*SCALE + bias, 67MB

// ---------------------------------------------------------------------------
// helpers
// ---------------------------------------------------------------------------
__device__ __forceinline__ uint32_t smem_u32(const void* p) {
    uint32_t a;
    asm("{ .reg .u64 t; cvta.to.shared.u64 t, %1; cvt.u32.u64 %0, t; }" : "=r"(a) : "l"(p));
    return a;
}
__device__ __forceinline__ void cp_async16(uint32_t dst, const void* src) {
    asm volatile("cp.async.cg.shared.global [%0], [%1], 16;" :: "r"(dst), "l"(src) : "memory");
}
__device__ __forceinline__ void cp_async4(uint32_t dst, const void* src) {
    asm volatile("cp.async.ca.shared.global [%0], [%1], 4;" :: "r"(dst), "l"(src) : "memory");
}
#define CP_COMMIT() asm volatile("cp.async.commit_group;" ::: "memory")
#define CP_WAIT(n)  asm volatile("cp.async.wait_group %0;" :: "n"(n) : "memory")

__device__ __forceinline__ void ldm_x4(uint32_t* r, uint32_t addr) {
    asm volatile("ldmatrix.sync.aligned.m8n8.x4.shared.b16 {%0,%1,%2,%3}, [%4];"
                 : "=r"(r[0]), "=r"(r[1]), "=r"(r[2]), "=r"(r[3]) : "r"(addr));
}
__device__ __forceinline__ void ldm_x4t(uint32_t* r, uint32_t addr) {
    asm volatile("ldmatrix.sync.aligned.m8n8.x4.trans.shared.b16 {%0,%1,%2,%3}, [%4];"
                 : "=r"(r[0]), "=r"(r[1]), "=r"(r[2]), "=r"(r[3]) : "r"(addr));
}
__device__ __forceinline__ void mma_f16(float* c, const uint32_t* a, const uint32_t* b) {
    asm volatile("mma.sync.aligned.m16n8k16.row.col.f32.f16.f16.f32 "
                 "{%0,%1,%2,%3}, {%4,%5,%6,%7}, {%8,%9}, {%0,%1,%2,%3};"
                 : "+f"(c[0]), "+f"(c[1]), "+f"(c[2]), "+f"(c[3])
                 : "r"(a[0]), "r"(a[1]), "r"(a[2]), "r"(a[3]), "r"(b[0]), "r"(b[1]));
}
__device__ __forceinline__ uint32_t h2u(__half2 h) { return *reinterpret_cast<uint32_t*>(&h); }

#define SCALE_F 11.313708498984761f   // sqrt(2*dh)

// ---------------------------------------------------------------------------
// Fused prep: pe + w_pos split + w_tok split + layernorm (all independent)
// ---------------------------------------------------------------------------
__device__ __forceinline__ void split4_body(const float4* __restrict__ src,
                                            uint32_t* __restrict__ hi,
                                            uint32_t* __restrict__ lo, int i) {
    float4 v = src[i];
    __half2 h0 = __floats2half2_rn(v.x, v.y);
    __half2 h1 = __floats2half2_rn(v.z, v.w);
    __half2 l0 = __floats2half2_rn(v.x - __low2float(h0), v.y - __high2float(h0));
    __half2 l1 = __floats2half2_rn(v.z - __low2float(h1), v.w - __high2float(h1));
    hi[2 * i] = h2u(h0); hi[2 * i + 1] = h2u(h1);
    lo[2 * i] = h2u(l0); lo[2 * i + 1] = h2u(l1);
}

__global__ void __launch_bounds__(256) prep_kernel(const float* __restrict__ w_pos,
                                                   const float* __restrict__ w_tok,
                                                   const float* __restrict__ x,
                                                   const float* __restrict__ gamma,
                                                   const float* __restrict__ beta) {
    const int bx = blockIdx.x, t = threadIdx.x;
    if (bx < 1024) {
        int s = bx;
        for (int d = t; d < D_MOD; d += 256) {
            int i = d >> 1;
            float div = expf((float)(2 * i) * (-9.210340371976184f / (float)D_MOD));
            float ang = (float)s * div;
            float v = (d & 1) ? cosf(ang) : sinf(ang);
            __half h = __float2half_rn(v);
            g_pe_hi[s * D_MOD + d] = h;
            g_pe_lo[s * D_MOD + d] = __float2half_rn(v - __half2float(h));
        }
    } else if (bx < 3072) {
        split4_body((const float4*)w_pos, (uint32_t*)g_wpos_hi, (uint32_t*)g_wpos_lo,
                    (bx - 1024) * 256 + t);
    } else if (bx < 6144) {
        split4_body((const float4*)w_tok, (uint32_t*)g_wtok_hi, (uint32_t*)g_wtok_lo,
                    (bx - 3072) * 256 + t);
    } else {
        const int row = bx - 6144;
        const float* xr = x + (size_t)row * D_MOD;
        const int lane = t & 31, wid = t >> 5;
        __shared__ float red[8];

        float v[4];
        float s = 0.f;
#pragma unroll
        for (int i = 0; i < 4; i++) { v[i] = xr[t + i * 256]; s += v[i]; }
#pragma unroll
        for (int o = 16; o > 0; o >>= 1) s += __shfl_xor_sync(0xffffffffu, s, o);
        if (lane == 0) red[wid] = s;
        __syncthreads();
        float tot = 0.f;
#pragma unroll
        for (int i = 0; i < 8; i++) tot += red[i];
        float mean = tot * (1.f / 1024.f);

        float sq = 0.f;
#pragma unroll
        for (int i = 0; i < 4; i++) { float d = v[i] - mean; sq += d * d; }
#pragma unroll
        for (int o = 16; o > 0; o >>= 1) sq += __shfl_xor_sync(0xffffffffu, sq, o);
        __syncthreads();
        if (lane == 0) red[wid] = sq;
        __syncthreads();
        float tot2 = 0.f;
#pragma unroll
        for (int i = 0; i < 8; i++) tot2 += red[i];
        float rstd = rsqrtf(tot2 * (1.f / 1024.f) + 1e-5f);

#pragma unroll
        for (int i = 0; i < 4; i++) {
            int c = t + i * 256;
            float y = (v[i] - mean) * rstd * gamma[c] + beta[c];
            __half h = __float2half_rn(y);
            g_xn_hi[(size_t)row * D_MOD + c] = h;
            g_xn_lo[(size_t)row * D_MOD + c] = __float2half_rn(y - __half2float(h));
        }
    }
}

// ---------------------------------------------------------------------------
// mma.sync fp16x2-split NT GEMM body (R10-proven), forced occupancy 2
// ---------------------------------------------------------------------------
#define OPBUF 10240
#define GEMM_SMEM (8 * OPBUF)

__device__ __forceinline__ void gemm_body(
    const __half* __restrict__ Ahi, const __half* __restrict__ Alo,
    const __half* __restrict__ Bhi, const __half* __restrict__ Blo,
    __half* __restrict__ Chi, __half* __restrict__ Clo,
    int N, int K, int m0, int n0, bool full, char* sm)
{
    const uint32_t sb = smem_u32(sm);
    const int tid = threadIdx.x;
    const int lane = tid & 31, wid = tid >> 5;
    const int wm = wid >> 2, wn = wid & 3;

    float acc[4][4][4];
#pragma unroll
    for (int i = 0; i < 4; i++)
#pragma unroll
        for (int j = 0; j < 4; j++)
#pragma unroll
            for (int r = 0; r < 4; r++) acc[i][j][r] = 0.f;

    const __half* srcs[4] = {Ahi, Alo, Bhi, Blo};
    const int rows0[4] = {m0, m0, n0, n0};
    const int NCH = K >> 5;
    const int lj = lane >> 3, lr = lane & 7;

#pragma unroll
    for (int op = 0; op < 4; op++) {
        if (op == 1 && !full) continue;
#pragma unroll
        for (int it = 0; it < 2; it++) {
            int e = tid + (it << 8);
            int r = e >> 2, cs = e & 3;
            cp_async16(sb + op * OPBUF + r * 80 + cs * 16,
                       srcs[op] + (size_t)(rows0[op] + r) * K + (cs << 3));
        }
    }
    CP_COMMIT();

    for (int i = 0; i < NCH; i++) {
        const int s = i & 1;
        if (i + 1 < NCH) {
            const int s2 = s ^ 1, k0 = (i + 1) << 5;
#pragma unroll
            for (int op = 0; op < 4; op++) {
                if (op == 1 && !full) continue;
#pragma unroll
                for (int it = 0; it < 2; it++) {
                    int e = tid + (it << 8);
                    int r = e >> 2, cs = e & 3;
                    cp_async16(sb + (s2 * 4 + op) * OPBUF + r * 80 + cs * 16,
                               srcs[op] + (size_t)(rows0[op] + r) * K + k0 + (cs << 3));
                }
            }
            CP_COMMIT();
            CP_WAIT(1);
        } else {
            CP_WAIT(0);
        }
        __syncthreads();

        const uint32_t ah_b = sb + (s * 4 + 0) * OPBUF;
        const uint32_t al_b = sb + (s * 4 + 1) * OPBUF;
        const uint32_t bh_b = sb + (s * 4 + 2) * OPBUF;
        const uint32_t bl_b = sb + (s * 4 + 3) * OPBUF;

#pragma unroll
        for (int kk = 0; kk < 32; kk += 16) {
            uint32_t ah[4][4], al[4][4];
#pragma unroll
            for (int tm = 0; tm < 4; tm++) {
                int m = wm * 64 + tm * 16 + (lj & 1) * 8 + lr;
                int k = kk + (lj >> 1) * 8;
                ldm_x4(ah[tm], ah_b + m * 80 + k * 2);
                if (full) ldm_x4(al[tm], al_b + m * 80 + k * 2);
            }
            uint32_t bh[2][4], bl[2][4];
#pragma unroll
            for (int tn = 0; tn < 2; tn++) {
                int n = wn * 32 + tn * 16 + (lj >> 1) * 8 + lr;
                int k = kk + (lj & 1) * 8;
                ldm_x4(bh[tn], bh_b + n * 80 + k * 2);
                ldm_x4(bl[tn], bl_b + n * 80 + k * 2);
            }
#pragma unroll
            for (int tm = 0; tm < 4; tm++)
#pragma unroll
                for (int t8 = 0; t8 < 4; t8++) {
                    uint32_t bhr[2] = {bh[t8 >> 1][2 * (t8 & 1)], bh[t8 >> 1][2 * (t8 & 1) + 1]};
                    uint32_t blr[2] = {bl[t8 >> 1][2 * (t8 & 1)], bl[t8 >> 1][2 * (t8 & 1) + 1]};
                    mma_f16(acc[tm][t8], ah[tm], bhr);
                    mma_f16(acc[tm][t8], ah[tm], blr);
                    if (full) mma_f16(acc[tm][t8], al[tm], bhr);
                }
        }
        __syncthreads();
    }

#pragma unroll
    for (int tm = 0; tm < 4; tm++) {
        int m = m0 + wm * 64 + tm * 16 + (lane >> 2);
#pragma unroll
        for (int t8 = 0; t8 < 4; t8++) {
            int n = n0 + wn * 32 + t8 * 8 + 2 * (lane & 3);
            float v0 = acc[tm][t8][0], v1 = acc[tm][t8][1];
            float v2 = acc[tm][t8][2], v3 = acc[tm][t8][3];
            __half2 h01 = __floats2half2_rn(v0, v1);
            __half2 h23 = __floats2half2_rn(v2, v3);
            *(__half2*)(Chi + (size_t)m * N + n) = h01;
            *(__half2*)(Chi + (size_t)(m + 8) * N + n) = h23;
            if (full) {
                __half2 l01 = __floats2half2_rn(v0 - __low2float(h01), v1 - __high2float(h01));
                __half2 l23 = __floats2half2_rn(v2 - __low2float(h23), v3 - __high2float(h23));
                *(__half2*)(Clo + (size_t)m * N + n) = l01;
                *(__half2*)(Clo + (size_t)(m + 8) * N + n) = l23;
            }
        }
    }
}

__global__ void __launch_bounds__(256, 2) gemm_merged() {
    extern __shared__ char sm[];
    int bx = blockIdx.x;
    if (bx < 768) {
        int n0 = (bx % 24) * 128, m0 = (bx / 24) * 128;
        gemm_body(g_xn_hi, g_xn_lo, g_wtok_hi, g_wtok_lo, g_th, g_tl,
                  3 * D_MOD, D_MOD, m0, n0, n0 < 2 * D_MOD, sm);
    } else {
        int bp = bx - 768;
        int n0 = (bp % 16) * 128, m0 = (bp / 16) * 128;
        gemm_body(g_pe_hi, g_pe_lo, g_wpos_hi, g_wpos_lo, g_ph, g_pl,
                  2 * D_MOD, D_MOD, m0, n0, true, sm);
    }
}

// ---------------------------------------------------------------------------
// P0[h,q,k] = (pos_q . pos_k) * SCALE + bias_table[k-q+1024, h]
// ---------------------------------------------------------------------------
#define PA_SMEM (4 * 18432 + 1024)

__global__ void __launch_bounds__(256) posattn_kernel(const float* __restrict__ bias_table) {
    extern __shared__ char sm[];
    const uint32_t sb = smem_u32(sm);
    const int tid = threadIdx.x, lane = tid & 31, wid = tid >> 5;
    const int wm = wid >> 2, wn = wid & 3;
    const int h = blockIdx.z, q0 = blockIdx.y * 128, k0 = blockIdx.x * 128;
    const int hc = h * 64;
    const int lj = lane >> 3, lr = lane & 7;

#pragma unroll
    for (int it = 0; it < 4; it++) {
        int e = tid + (it << 8);
        int r = e >> 3, c = e & 7;
        size_t qa = (size_t)(q0 + r) * 2048 + 1024 + hc + c * 8;
        size_t ka = (size_t)(k0 + r) * 2048 + hc + c * 8;
        uint32_t o = r * 144 + c * 16;
        cp_async16(sb + o, g_ph + qa);
        cp_async16(sb + 18432 + o, g_pl + qa);
        cp_async16(sb + 36864 + o, g_ph + ka);
        cp_async16(sb + 55296 + o, g_pl + ka);
    }
    {
        int rel = k0 - q0 + 897 + tid;
        rel = rel < 0 ? 0 : (rel > 2047 ? 2047 : rel);
        cp_async4(sb + 73728 + tid * 4, bias_table + rel * N_H + h);
    }
    CP_COMMIT();
    CP_WAIT(0);
    __syncthreads();

    float acc[4][4][4];
#pragma unroll
    for (int i = 0; i < 4; i++)
#pragma unroll
        for (int j = 0; j < 4; j++)
#pragma unroll
            for (int r = 0; r < 4; r++) acc[i][j][r] = 0.f;

#pragma unroll
    for (int kk = 0; kk < 4; kk++) {
        uint32_t ah[4][4], al[4][4];
#pragma unroll
        for (int tm = 0; tm < 4; tm++) {
            int m = wm * 64 + tm * 16 + (lj & 1) * 8 + lr;
            int k = kk * 16 + (lj >> 1) * 8;
            ldm_x4(ah[tm], sb + m * 144 + k * 2);
            ldm_x4(al[tm], sb + 18432 + m * 144 + k * 2);
        }
        uint32_t bh[2][4], bl[2][4];
#pragma unroll
        for (int tn = 0; tn < 2; tn++) {
            int n = wn * 32 + tn * 16 + (lj >> 1) * 8 + lr;
            int k = kk * 16 + (lj & 1) * 8;
            ldm_x4(bh[tn], sb + 36864 + n * 144 + k * 2);
            ldm_x4(bl[tn], sb + 55296 + n * 144 + k * 2);
        }
#pragma unroll
        for (int tm = 0; tm < 4; tm++)
#pragma unroll
            for (int t8 = 0; t8 < 4; t8++) {
                uint32_t bhr[2] = {bh[t8 >> 1][2 * (t8 & 1)], bh[t8 >> 1][2 * (t8 & 1) + 1]};
                uint32_t blr[2] = {bl[t8 >> 1][2 * (t8 & 1)], bl[t8 >> 1][2 * (t8 & 1) + 1]};
                mma_f16(acc[tm][t8], ah[tm], bhr);
                mma_f16(acc[tm][t8], ah[tm], blr);
                mma_f16(acc[tm][t8], al[tm], bhr);
            }
    }

    const float* bias_s = (const float*)(sm + 73728);
    float* P0b = g_P0 + ((size_t)h << 20);
#pragma unroll
    for (int tm = 0; tm < 4; tm++) {
        int q = wm * 64 + tm * 16 + (lane >> 2);
#pragma unroll
        for (int t8 = 0; t8 < 4; t8++) {
            int k = wn * 32 + t8 * 8 + 2 * (lane & 3);
            int idx = k - q + 127;
            float o0 = acc[tm][t8][0] * SCALE_F + bias_s[idx];
            float o1 = acc[tm][t8][1] * SCALE_F + bias_s[idx + 1];
            float o2 = acc[tm][t8][2] * SCALE_F + bias_s[idx - 8];
            float o3 = acc[tm][t8][3] * SCALE_F + bias_s[idx - 7];
            *(float2*)(P0b + (size_t)(q0 + q) * 1024 + k0 + k) = make_float2(o0, o1);
            *(float2*)(P0b + (size_t)(q0 + q + 8) * 1024 + k0 + k) = make_float2(o2, o3);
        }
    }
}

// ---------------------------------------------------------------------------
// Flash attention with deferred-PV pipelining: at tile kt, PV(kt-1) MMAs are
// issued during softmax(kt) so the tensor pipe stays fed. Split prefetch:
// K+P0(kt+1) at iteration top, V(kt+1) after the post-PV barrier; top wait is
// CP_WAIT(1) so the V group keeps a full iteration of latency cover.
// ---------------------------------------------------------------------------
#define KROW2 144
#define KB2 9216
#define P0ROW 272
#define STG (3 * KB2 + 64 * P0ROW)   // 45056
#define FL_SMEM (2 * STG)            // 90112

__device__ __forceinline__ void fl_prefetch_KP(uint32_t sb, int b, int h, int hc,
                                               int q0, int k0, int s, int tid) {
    const uint32_t kb = sb + s * STG;
    const size_t rb = ((size_t)b * S_LEN + k0) * 3072;
#pragma unroll
    for (int it = 0; it < 4; it++) {
        int e = tid + (it << 7);
        int k = e >> 3, c = e & 7;
        size_t so = rb + (size_t)k * 3072 + hc + c * 8;
        uint32_t o = k * KROW2 + c * 16;
        cp_async16(kb + o, g_th + so);
        cp_async16(kb + KB2 + o, g_tl + so);
    }
    const float* p0src = g_P0 + ((size_t)h << 20) + (size_t)q0 * 1024 + k0;
#pragma unroll
    for (int it = 0; it < 8; it++) {
        int e = tid + (it << 7);
        int r = e >> 4, c = e & 15;
        cp_async16(kb + 3 * KB2 + r * P0ROW + c * 16, p0src + (size_t)r * 1024 + c * 4);
    }
}

__device__ __forceinline__ void fl_prefetch_V(uint32_t sb, int b, int hc,
                                              int k0, int s, int tid) {
    const uint32_t vb = sb + s * STG + 2 * KB2;
    const size_t rb = ((size_t)b * S_LEN + k0) * 3072;
#pragma unroll
    for (int it = 0; it < 4; it++) {
        int e = tid + (it << 7);
        int k = e >> 3, c = e & 7;
        size_t sv = rb + (size_t)k * 3072 + 2048 + hc + c * 8;
        cp_async16(vb + k * KROW2 + c * 16, g_th + sv);
    }
}

__global__ void __launch_bounds__(128, 2) flash_kernel(float* __restrict__ out) {
    extern __shared__ char sm[];
    const uint32_t sb = smem_u32(sm);
    const int tid = threadIdx.x, lane = tid & 31, wid = tid >> 5;
    const int lj = lane >> 3, lr = lane & 7;
    const int b = blockIdx.z, h = blockIdx.y, q0 = blockIdx.x * 64;
    const int hc = h * 64;
    const int m0w = wid * 16;

    // --- stage Q through smem (K-slot areas), then to regs ---
    {
        const size_t rb = ((size_t)b * S_LEN + q0) * 3072;
#pragma unroll
        for (int it = 0; it < 4; it++) {
            int e = tid + (it << 7);
            int q = e >> 3, c = e & 7;
            size_t so = rb + (size_t)q * 3072 + 1024 + hc + c * 8;
            cp_async16(sb + q * KROW2 + c * 16, g_th + so);
            cp_async16(sb + STG + q * KROW2 + c * 16, g_tl + so);
        }
        CP_COMMIT();
        CP_WAIT(0);
        __syncthreads();
    }
    uint32_t qh[4][4], qlo[4][4];
#pragma unroll
    for (int dk = 0; dk < 4; dk++) {
        uint32_t qa = sb + (m0w + (lj & 1) * 8 + lr) * KROW2 + (dk * 16 + (lj >> 1) * 8) * 2;
        ldm_x4(qh[dk], qa);
        ldm_x4(qlo[dk], qa + STG);
    }
    __syncthreads();

    // prologue prefetch: GK0 then GV0 (two groups)
    fl_prefetch_KP(sb, b, h, hc, q0, 0, 0, tid);
    CP_COMMIT();
    fl_prefetch_V(sb, b, hc, 0, 0, tid);
    CP_COMMIT();

    float O[8][4];
#pragma unroll
    for (int i = 0; i < 8; i++)
#pragma unroll
        for (int j = 0; j < 4; j++) O[i][j] = 0.f;
    float m0 = -INFINITY, m1 = -INFINITY, l0 = 0.f, l1 = 0.f;
    uint32_t ph0[8], ph1[8];   // P(kt-1), consumed one iteration late

    const float LOG2E = 1.4426950408889634f;
    const int NT = S_LEN / 64;
    const int qr = m0w + (lane >> 2);

    for (int kt = 0; kt < NT; kt++) {
        const int s = kt & 1;

        // top: K/P0(kt) ready (GV(kt) may still be in flight -> CP_WAIT(1))
        CP_WAIT(1);
        __syncthreads();

        // issue K+P0 for kt+1 into the other stage (its K slot was consumed
        // by QK(kt-1); barrier at end of kt-1 ordered all reads)
        if (kt + 1 < NT) {
            fl_prefetch_KP(sb, b, h, hc, q0, (kt + 1) * 64, s ^ 1, tid);
            CP_COMMIT();
        }

        const uint32_t khb = sb + s * STG;
        const char* p0s = sm + s * STG + 3 * KB2;

        // ---- S = Q K^T (hi/lo 3-pass, de=64) ----
        float Sa[8][4];
#pragma unroll
        for (int i = 0; i < 8; i++)
#pragma unroll
            for (int j = 0; j < 4; j++) Sa[i][j] = 0.f;

#pragma unroll
        for (int dk = 0; dk < 4; dk++) {
#pragma unroll
            for (int ng = 0; ng < 4; ng++) {
                uint32_t bh[4], bl[4];
                uint32_t ka = khb + (ng * 16 + (lj >> 1) * 8 + lr) * KROW2 + (dk * 16 + (lj & 1) * 8) * 2;
                ldm_x4(bh, ka);
                ldm_x4(bl, ka + KB2);
                uint32_t b0[2] = {bh[0], bh[1]}, c0[2] = {bl[0], bl[1]};
                mma_f16(Sa[2 * ng], qh[dk], b0);
                mma_f16(Sa[2 * ng], qh[dk], c0);
                mma_f16(Sa[2 * ng], qlo[dk], b0);
                uint32_t b1[2] = {bh[2], bh[3]}, c1[2] = {bl[2], bl[3]};
                mma_f16(Sa[2 * ng + 1], qh[dk], b1);
                mma_f16(Sa[2 * ng + 1], qh[dk], c1);
                mma_f16(Sa[2 * ng + 1], qlo[dk], b1);
            }
        }

        // ---- add P0, row max ----
        float mx0 = -INFINITY, mx1 = -INFINITY;
#pragma unroll
        for (int tt = 0; tt < 8; tt++) {
            int kl = 8 * tt + 2 * (lane & 3);
            float2 b0 = *(const float2*)(p0s + qr * P0ROW + kl * 4);
            float2 b1 = *(const float2*)(p0s + (qr + 8) * P0ROW + kl * 4);
            float s0 = Sa[tt][0] * SCALE_F + b0.x;
            float s1 = Sa[tt][1] * SCALE_F + b0.y;
            float s2 = Sa[tt][2] * SCALE_F + b1.x;
            float s3 = Sa[tt][3] * SCALE_F + b1.y;
            Sa[tt][0] = s0; Sa[tt][1] = s1; Sa[tt][2] = s2; Sa[tt][3] = s3;
            mx0 = fmaxf(mx0, fmaxf(s0, s1));
            mx1 = fmaxf(mx1, fmaxf(s2, s3));
        }
        mx0 = fmaxf(mx0, __shfl_xor_sync(0xffffffffu, mx0, 1));
        mx0 = fmaxf(mx0, __shfl_xor_sync(0xffffffffu, mx0, 2));
        mx1 = fmaxf(mx1, __shfl_xor_sync(0xffffffffu, mx1, 1));
        mx1 = fmaxf(mx1, __shfl_xor_sync(0xffffffffu, mx1, 2));
        float mn0 = fmaxf(m0, mx0), mn1 = fmaxf(m1, mx1);
        float a0 = exp2f((m0 - mn0) * LOG2E), a1 = exp2f((m1 - mn1) * LOG2E);
        m0 = mn0; m1 = mn1;

        // ---- deferred PV(kt-1): tensor work overlapping softmax ----
        if (kt > 0) {
            const uint32_t vprev = sb + (s ^ 1) * STG + 2 * KB2;
#pragma unroll
            for (int ck = 0; ck < 4; ck++) {
                uint32_t Ah[4] = {ph0[2 * ck], ph1[2 * ck], ph0[2 * ck + 1], ph1[2 * ck + 1]};
#pragma unroll
                for (int dg = 0; dg < 4; dg++) {
                    uint32_t vh[4];
                    uint32_t va = vprev + (ck * 16 + (lj & 1) * 8 + lr) * KROW2 + (dg * 16 + (lj >> 1) * 8) * 2;
                    ldm_x4t(vh, va);
                    uint32_t v0[2] = {vh[0], vh[1]};
                    mma_f16(O[2 * dg], Ah, v0);
                    uint32_t v1[2] = {vh[2], vh[3]};
                    mma_f16(O[2 * dg + 1], Ah, v1);
                }
            }
        }

        // ---- exp, pack new P, row sums (interleaves with PV drain) ----
        float r0 = 0.f, r1 = 0.f;
#pragma unroll
        for (int tt = 0; tt < 8; tt++) {
            float p0 = exp2f((Sa[tt][0] - m0) * LOG2E);
            float p1 = exp2f((Sa[tt][1] - m0) * LOG2E);
            float p2 = exp2f((Sa[tt][2] - m1) * LOG2E);
            float p3 = exp2f((Sa[tt][3] - m1) * LOG2E);
            r0 += p0 + p1; r1 += p2 + p3;
            ph0[tt] = h2u(__floats2half2_rn(p0, p1));
            ph1[tt] = h2u(__floats2half2_rn(p2, p3));
        }
        r0 += __shfl_xor_sync(0xffffffffu, r0, 1);
        r0 += __shfl_xor_sync(0xffffffffu, r0, 2);
        r1 += __shfl_xor_sync(0xffffffffu, r1, 1);
        r1 += __shfl_xor_sync(0xffffffffu, r1, 2);
        l0 = l0 * a0 + r0;
        l1 = l1 * a1 + r1;

        // ---- scale O AFTER PV(kt-1) (recurrence: O=(O+P(kt-1)V)*alpha) ----
#pragma unroll
        for (int dt = 0; dt < 8; dt++) {
            O[dt][0] *= a0; O[dt][1] *= a0; O[dt][2] *= a1; O[dt][3] *= a1;
        }

        __syncthreads();   // all warps done with stage s^1 (PV reads)
        if (kt + 1 < NT) {
            fl_prefetch_V(sb, b, hc, (kt + 1) * 64, s ^ 1, tid);
            CP_COMMIT();
        }
    }

    // ---- final PV(NT-1) ----
    CP_WAIT(0);
    __syncthreads();
    {
        const uint32_t vlast = sb + ((NT - 1) & 1) * STG + 2 * KB2;
#pragma unroll
        for (int ck = 0; ck < 4; ck++) {
            uint32_t Ah[4] = {ph0[2 * ck], ph1[2 * ck], ph0[2 * ck + 1], ph1[2 * ck + 1]};
#pragma unroll
            for (int dg = 0; dg < 4; dg++) {
                uint32_t vh[4];
                uint32_t va = vlast + (ck * 16 + (lj & 1) * 8 + lr) * KROW2 + (dg * 16 + (lj >> 1) * 8) * 2;
                ldm_x4t(vh, va);
                uint32_t v0[2] = {vh[0], vh[1]};
                mma_f16(O[2 * dg], Ah, v0);
                uint32_t v1[2] = {vh[2], vh[3]};
                mma_f16(O[2 * dg + 1], Ah, v1);
            }
        }
    }

    float inv0 = 1.f / l0, inv1 = 1.f / l1;
    size_t row = (size_t)b * S_LEN + q0 + m0w + (lane >> 2);
#pragma unroll
    for (int dt = 0; dt < 8; dt++) {
        int n = hc + dt * 8 + 2 * (lane & 3);
        *(float2*)(out + row * D_MOD + n) = make_float2(O[dt][0] * inv0, O[dt][1] * inv0);
        *(float2*)(out + (row + 8) * D_MOD + n) = make_float2(O[dt][2] * inv1, O[dt][3] * inv1);
    }
}

// ---------------------------------------------------------------------------
// Launch (single stream — block-range fusion)
// ---------------------------------------------------------------------------
extern "C" void kernel_launch(void* const* d_in, const int* in_sizes, int n_in,
                              void* d_out, int out_size) {
    const float* x          = (const float*)d_in[0];
    const float* gamma      = (const float*)d_in[1];
    const float* beta       = (const float*)d_in[2];
    const float* w_pos      = (const float*)d_in[3];
    const float* w_tok      = (const float*)d_in[4];
    const float* bias_table = (const float*)d_in[5];
    float* out = (float*)d_out;

    cudaFuncSetAttribute(gemm_merged, cudaFuncAttributeMaxDynamicSharedMemorySize, GEMM_SMEM);
    cudaFuncSetAttribute(posattn_kernel, cudaFuncAttributeMaxDynamicSharedMemorySize, PA_SMEM);
    cudaFuncSetAttribute(flash_kernel, cudaFuncAttributeMaxDynamicSharedMemorySize, FL_SMEM);

    // fused elementwise: pe + w_pos split + w_tok split + layernorm
    prep_kernel<<<10240, 256>>>(w_pos, w_tok, x, gamma, beta);
    // merged GEMMs: tok (768 blocks) + pos (128 blocks), occ 2
    gemm_merged<<<896, 256, GEMM_SMEM>>>();
    // P0 = pos_attn*SCALE + bias (batch-independent)
    posattn_kernel<<<dim3(8, 8, 16), 256, PA_SMEM>>>(bias_table);
    // flash attention (deferred-PV pipelined, occ 2)
    flash_kernel<<<dim3(S_LEN / 64, N_H, B_SZ), 128, FL_SMEM>>>(out);
}

// round 17
// speedup vs baseline: 1.1006x; 1.0019x over previous
#include <cuda_runtime.h>
#include <cuda_fp16.h>
#include <math.h>
#include <stdint.h>

#define S_LEN 1024
#define D_MOD 1024
#define B_SZ 4
#define N_H 16
#define MAXLEN 1024

// ---------------------------------------------------------------------------
// Scratch (device globals — no allocations allowed)
// ---------------------------------------------------------------------------
__device__ __half g_pe_hi[S_LEN * D_MOD],        g_pe_lo[S_LEN * D_MOD];
__device__ __half g_wpos_hi[2 * D_MOD * D_MOD],  g_wpos_lo[2 * D_MOD * D_MOD];
__device__ __half g_xn_hi[B_SZ * S_LEN * D_MOD], g_xn_lo[B_SZ * S_LEN * D_MOD];
__device__ __half g_wtok_hi[3 * D_MOD * D_MOD],  g_wtok_lo[3 * D_MOD * D_MOD];
__device__ __half g_ph[S_LEN * 2 * D_MOD], g_pl[S_LEN * 2 * D_MOD];                      // pos
__device__ __half g_th[(size_t)B_SZ * S_LEN * 3 * D_MOD], g_tl[(size_t)B_SZ * S_LEN * 3 * D_MOD]; // tok
__device__ float  g_P0[(size_t)N_H * S_LEN * S_LEN];      // pos_attn*SCALE + bias, 67MB

// ---------------------------------------------------------------------------
// helpers
// ---------------------------------------------------------------------------
__device__ __forceinline__ uint32_t smem_u32(const void* p) {
    uint32_t a;
    asm("{ .reg .u64 t; cvta.to.shared.u64 t, %1; cvt.u32.u64 %0, t; }" : "=r"(a) : "l"(p));
    return a;
}
__device__ __forceinline__ void cp_async16(uint32_t dst, const void* src) {
    asm volatile("cp.async.cg.shared.global [%0], [%1], 16;" :: "r"(dst), "l"(src) : "memory");
}
__device__ __forceinline__ void cp_async4(uint32_t dst, const void* src) {
    asm volatile("cp.async.ca.shared.global [%0], [%1], 4;" :: "r"(dst), "l"(src) : "memory");
}
#define CP_COMMIT() asm volatile("cp.async.commit_group;" ::: "memory")
#define CP_WAIT(n)  asm volatile("cp.async.wait_group %0;" :: "n"(n) : "memory")

__device__ __forceinline__ void ldm_x4(uint32_t* r, uint32_t addr) {
    asm volatile("ldmatrix.sync.aligned.m8n8.x4.shared.b16 {%0,%1,%2,%3}, [%4];"
                 : "=r"(r[0]), "=r"(r[1]), "=r"(r[2]), "=r"(r[3]) : "r"(addr));
}
__device__ __forceinline__ void ldm_x4t(uint32_t* r, uint32_t addr) {
    asm volatile("ldmatrix.sync.aligned.m8n8.x4.trans.shared.b16 {%0,%1,%2,%3}, [%4];"
                 : "=r"(r[0]), "=r"(r[1]), "=r"(r[2]), "=r"(r[3]) : "r"(addr));
}
__device__ __forceinline__ void mma_f16(float* c, const uint32_t* a, const uint32_t* b) {
    asm volatile("mma.sync.aligned.m16n8k16.row.col.f32.f16.f16.f32 "
                 "{%0,%1,%2,%3}, {%4,%5,%6,%7}, {%8,%9}, {%0,%1,%2,%3};"
                 : "+f"(c[0]), "+f"(c[1]), "+f"(c[2]), "+f"(c[3])
                 : "r"(a[0]), "r"(a[1]), "r"(a[2]), "r"(a[3]), "r"(b[0]), "r"(b[1]));
}
__device__ __forceinline__ uint32_t h2u(__half2 h) { return *reinterpret_cast<uint32_t*>(&h); }

#define SCALE_F 11.313708498984761f   // sqrt(2*dh)

// ---------------------------------------------------------------------------
// Fused prep: pe + w_pos split + w_tok split + layernorm (all independent)
// ---------------------------------------------------------------------------
__device__ __forceinline__ void split4_body(const float4* __restrict__ src,
                                            uint32_t* __restrict__ hi,
                                            uint32_t* __restrict__ lo, int i) {
    float4 v = src[i];
    __half2 h0 = __floats2half2_rn(v.x, v.y);
    __half2 h1 = __floats2half2_rn(v.z, v.w);
    __half2 l0 = __floats2half2_rn(v.x - __low2float(h0), v.y - __high2float(h0));
    __half2 l1 = __floats2half2_rn(v.z - __low2float(h1), v.w - __high2float(h1));
    hi[2 * i] = h2u(h0); hi[2 * i + 1] = h2u(h1);
    lo[2 * i] = h2u(l0); lo[2 * i + 1] = h2u(l1);
}

__global__ void __launch_bounds__(256) prep_kernel(const float* __restrict__ w_pos,
                                                   const float* __restrict__ w_tok,
                                                   const float* __restrict__ x,
                                                   const float* __restrict__ gamma,
                                                   const float* __restrict__ beta) {
    const int bx = blockIdx.x, t = threadIdx.x;
    if (bx < 1024) {
        // pe pairs: one expf + one sincosf per (2i, 2i+1) pair
        int s = bx;
        for (int p = t; p < D_MOD / 2; p += 256) {
            float div = expf((float)(2 * p) * (-9.210340371976184f / (float)D_MOD));
            float ang = (float)s * div;
            float sv, cv;
            sincosf(ang, &sv, &cv);
            __half hs = __float2half_rn(sv);
            __half hcv = __float2half_rn(cv);
            int d = 2 * p;
            g_pe_hi[s * D_MOD + d] = hs;
            g_pe_lo[s * D_MOD + d] = __float2half_rn(sv - __half2float(hs));
            g_pe_hi[s * D_MOD + d + 1] = hcv;
            g_pe_lo[s * D_MOD + d + 1] = __float2half_rn(cv - __half2float(hcv));
        }
    } else if (bx < 3072) {
        split4_body((const float4*)w_pos, (uint32_t*)g_wpos_hi, (uint32_t*)g_wpos_lo,
                    (bx - 1024) * 256 + t);
    } else if (bx < 6144) {
        split4_body((const float4*)w_tok, (uint32_t*)g_wtok_hi, (uint32_t*)g_wtok_lo,
                    (bx - 3072) * 256 + t);
    } else {
        const int row = bx - 6144;
        const float* xr = x + (size_t)row * D_MOD;
        const int lane = t & 31, wid = t >> 5;
        __shared__ float red[8];

        float v[4];
        float s = 0.f;
#pragma unroll
        for (int i = 0; i < 4; i++) { v[i] = xr[t + i * 256]; s += v[i]; }
#pragma unroll
        for (int o = 16; o > 0; o >>= 1) s += __shfl_xor_sync(0xffffffffu, s, o);
        if (lane == 0) red[wid] = s;
        __syncthreads();
        float tot = 0.f;
#pragma unroll
        for (int i = 0; i < 8; i++) tot += red[i];
        float mean = tot * (1.f / 1024.f);

        float sq = 0.f;
#pragma unroll
        for (int i = 0; i < 4; i++) { float d = v[i] - mean; sq += d * d; }
#pragma unroll
        for (int o = 16; o > 0; o >>= 1) sq += __shfl_xor_sync(0xffffffffu, sq, o);
        __syncthreads();
        if (lane == 0) red[wid] = sq;
        __syncthreads();
        float tot2 = 0.f;
#pragma unroll
        for (int i = 0; i < 8; i++) tot2 += red[i];
        float rstd = rsqrtf(tot2 * (1.f / 1024.f) + 1e-5f);

#pragma unroll
        for (int i = 0; i < 4; i++) {
            int c = t + i * 256;
            float y = (v[i] - mean) * rstd * gamma[c] + beta[c];
            __half h = __float2half_rn(y);
            g_xn_hi[(size_t)row * D_MOD + c] = h;
            g_xn_lo[(size_t)row * D_MOD + c] = __float2half_rn(y - __half2float(h));
        }
    }
}

// ---------------------------------------------------------------------------
// mma.sync fp16x2-split NT GEMM body (R10-proven), forced occupancy 2
// ---------------------------------------------------------------------------
#define OPBUF 10240
#define GEMM_SMEM (8 * OPBUF)

__device__ __forceinline__ void gemm_body(
    const __half* __restrict__ Ahi, const __half* __restrict__ Alo,
    const __half* __restrict__ Bhi, const __half* __restrict__ Blo,
    __half* __restrict__ Chi, __half* __restrict__ Clo,
    int N, int K, int m0, int n0, bool full, char* sm)
{
    const uint32_t sb = smem_u32(sm);
    const int tid = threadIdx.x;
    const int lane = tid & 31, wid = tid >> 5;
    const int wm = wid >> 2, wn = wid & 3;

    float acc[4][4][4];
#pragma unroll
    for (int i = 0; i < 4; i++)
#pragma unroll
        for (int j = 0; j < 4; j++)
#pragma unroll
            for (int r = 0; r < 4; r++) acc[i][j][r] = 0.f;

    const __half* srcs[4] = {Ahi, Alo, Bhi, Blo};
    const int rows0[4] = {m0, m0, n0, n0};
    const int NCH = K >> 5;
    const int lj = lane >> 3, lr = lane & 7;

#pragma unroll
    for (int op = 0; op < 4; op++) {
        if (op == 1 && !full) continue;
#pragma unroll
        for (int it = 0; it < 2; it++) {
            int e = tid + (it << 8);
            int r = e >> 2, cs = e & 3;
            cp_async16(sb + op * OPBUF + r * 80 + cs * 16,
                       srcs[op] + (size_t)(rows0[op] + r) * K + (cs << 3));
        }
    }
    CP_COMMIT();

    for (int i = 0; i < NCH; i++) {
        const int s = i & 1;
        if (i + 1 < NCH) {
            const int s2 = s ^ 1, k0 = (i + 1) << 5;
#pragma unroll
            for (int op = 0; op < 4; op++) {
                if (op == 1 && !full) continue;
#pragma unroll
                for (int it = 0; it < 2; it++) {
                    int e = tid + (it << 8);
                    int r = e >> 2, cs = e & 3;
                    cp_async16(sb + (s2 * 4 + op) * OPBUF + r * 80 + cs * 16,
                               srcs[op] + (size_t)(rows0[op] + r) * K + k0 + (cs << 3));
                }
            }
            CP_COMMIT();
            CP_WAIT(1);
        } else {
            CP_WAIT(0);
        }
        __syncthreads();

        const uint32_t ah_b = sb + (s * 4 + 0) * OPBUF;
        const uint32_t al_b = sb + (s * 4 + 1) * OPBUF;
        const uint32_t bh_b = sb + (s * 4 + 2) * OPBUF;
        const uint32_t bl_b = sb + (s * 4 + 3) * OPBUF;

#pragma unroll
        for (int kk = 0; kk < 32; kk += 16) {
            uint32_t ah[4][4], al[4][4];
#pragma unroll
            for (int tm = 0; tm < 4; tm++) {
                int m = wm * 64 + tm * 16 + (lj & 1) * 8 + lr;
                int k = kk + (lj >> 1) * 8;
                ldm_x4(ah[tm], ah_b + m * 80 + k * 2);
                if (full) ldm_x4(al[tm], al_b + m * 80 + k * 2);
            }
            uint32_t bh[2][4], bl[2][4];
#pragma unroll
            for (int tn = 0; tn < 2; tn++) {
                int n = wn * 32 + tn * 16 + (lj >> 1) * 8 + lr;
                int k = kk + (lj & 1) * 8;
                ldm_x4(bh[tn], bh_b + n * 80 + k * 2);
                ldm_x4(bl[tn], bl_b + n * 80 + k * 2);
            }
#pragma unroll
            for (int tm = 0; tm < 4; tm++)
#pragma unroll
                for (int t8 = 0; t8 < 4; t8++) {
                    uint32_t bhr[2] = {bh[t8 >> 1][2 * (t8 & 1)], bh[t8 >> 1][2 * (t8 & 1) + 1]};
                    uint32_t blr[2] = {bl[t8 >> 1][2 * (t8 & 1)], bl[t8 >> 1][2 * (t8 & 1) + 1]};
                    mma_f16(acc[tm][t8], ah[tm], bhr);
                    mma_f16(acc[tm][t8], ah[tm], blr);
                    if (full) mma_f16(acc[tm][t8], al[tm], bhr);
                }
        }
        __syncthreads();
    }

#pragma unroll
    for (int tm = 0; tm < 4; tm++) {
        int m = m0 + wm * 64 + tm * 16 + (lane >> 2);
#pragma unroll
        for (int t8 = 0; t8 < 4; t8++) {
            int n = n0 + wn * 32 + t8 * 8 + 2 * (lane & 3);
            float v0 = acc[tm][t8][0], v1 = acc[tm][t8][1];
            float v2 = acc[tm][t8][2], v3 = acc[tm][t8][3];
            __half2 h01 = __floats2half2_rn(v0, v1);
            __half2 h23 = __floats2half2_rn(v2, v3);
            *(__half2*)(Chi + (size_t)m * N + n) = h01;
            *(__half2*)(Chi + (size_t)(m + 8) * N + n) = h23;
            if (full) {
                __half2 l01 = __floats2half2_rn(v0 - __low2float(h01), v1 - __high2float(h01));
                __half2 l23 = __floats2half2_rn(v2 - __low2float(h23), v3 - __high2float(h23));
                *(__half2*)(Clo + (size_t)m * N + n) = l01;
                *(__half2*)(Clo + (size_t)(m + 8) * N + n) = l23;
            }
        }
    }
}

__global__ void __launch_bounds__(256, 2) gemm_merged() {
    extern __shared__ char sm[];
    int bx = blockIdx.x;
    if (bx < 768) {
        int n0 = (bx % 24) * 128, m0 = (bx / 24) * 128;
        gemm_body(g_xn_hi, g_xn_lo, g_wtok_hi, g_wtok_lo, g_th, g_tl,
                  3 * D_MOD, D_MOD, m0, n0, n0 < 2 * D_MOD, sm);
    } else {
        int bp = bx - 768;
        int n0 = (bp % 16) * 128, m0 = (bp / 16) * 128;
        gemm_body(g_pe_hi, g_pe_lo, g_wpos_hi, g_wpos_lo, g_ph, g_pl,
                  2 * D_MOD, D_MOD, m0, n0, true, sm);
    }
}

// ---------------------------------------------------------------------------
// P0[h,q,k] = (pos_q . pos_k) * SCALE + bias_table[k-q+1024, h]
// ---------------------------------------------------------------------------
#define PA_SMEM (4 * 18432 + 1024)

__global__ void __launch_bounds__(256) posattn_kernel(const float* __restrict__ bias_table) {
    extern __shared__ char sm[];
    const uint32_t sb = smem_u32(sm);
    const int tid = threadIdx.x, lane = tid & 31, wid = tid >> 5;
    const int wm = wid >> 2, wn = wid & 3;
    const int h = blockIdx.z, q0 = blockIdx.y * 128, k0 = blockIdx.x * 128;
    const int hc = h * 64;
    const int lj = lane >> 3, lr = lane & 7;

#pragma unroll
    for (int it = 0; it < 4; it++) {
        int e = tid + (it << 8);
        int r = e >> 3, c = e & 7;
        size_t qa = (size_t)(q0 + r) * 2048 + 1024 + hc + c * 8;
        size_t ka = (size_t)(k0 + r) * 2048 + hc + c * 8;
        uint32_t o = r * 144 + c * 16;
        cp_async16(sb + o, g_ph + qa);
        cp_async16(sb + 18432 + o, g_pl + qa);
        cp_async16(sb + 36864 + o, g_ph + ka);
        cp_async16(sb + 55296 + o, g_pl + ka);
    }
    {
        int rel = k0 - q0 + 897 + tid;
        rel = rel < 0 ? 0 : (rel > 2047 ? 2047 : rel);
        cp_async4(sb + 73728 + tid * 4, bias_table + rel * N_H + h);
    }
    CP_COMMIT();
    CP_WAIT(0);
    __syncthreads();

    float acc[4][4][4];
#pragma unroll
    for (int i = 0; i < 4; i++)
#pragma unroll
        for (int j = 0; j < 4; j++)
#pragma unroll
            for (int r = 0; r < 4; r++) acc[i][j][r] = 0.f;

#pragma unroll
    for (int kk = 0; kk < 4; kk++) {
        uint32_t ah[4][4], al[4][4];
#pragma unroll
        for (int tm = 0; tm < 4; tm++) {
            int m = wm * 64 + tm * 16 + (lj & 1) * 8 + lr;
            int k = kk * 16 + (lj >> 1) * 8;
            ldm_x4(ah[tm], sb + m * 144 + k * 2);
            ldm_x4(al[tm], sb + 18432 + m * 144 + k * 2);
        }
        uint32_t bh[2][4], bl[2][4];
#pragma unroll
        for (int tn = 0; tn < 2; tn++) {
            int n = wn * 32 + tn * 16 + (lj >> 1) * 8 + lr;
            int k = kk * 16 + (lj & 1) * 8;
            ldm_x4(bh[tn], sb + 36864 + n * 144 + k * 2);
            ldm_x4(bl[tn], sb + 55296 + n * 144 + k * 2);
        }
#pragma unroll
        for (int tm = 0; tm < 4; tm++)
#pragma unroll
            for (int t8 = 0; t8 < 4; t8++) {
                uint32_t bhr[2] = {bh[t8 >> 1][2 * (t8 & 1)], bh[t8 >> 1][2 * (t8 & 1) + 1]};
                uint32_t blr[2] = {bl[t8 >> 1][2 * (t8 & 1)], bl[t8 >> 1][2 * (t8 & 1) + 1]};
                mma_f16(acc[tm][t8], ah[tm], bhr);
                mma_f16(acc[tm][t8], ah[tm], blr);
                mma_f16(acc[tm][t8], al[tm], bhr);
            }
    }

    const float* bias_s = (const float*)(sm + 73728);
    float* P0b = g_P0 + ((size_t)h << 20);
#pragma unroll
    for (int tm = 0; tm < 4; tm++) {
        int q = wm * 64 + tm * 16 + (lane >> 2);
#pragma unroll
        for (int t8 = 0; t8 < 4; t8++) {
            int k = wn * 32 + t8 * 8 + 2 * (lane & 3);
            int idx = k - q + 127;
            float o0 = acc[tm][t8][0] * SCALE_F + bias_s[idx];
            float o1 = acc[tm][t8][1] * SCALE_F + bias_s[idx + 1];
            float o2 = acc[tm][t8][2] * SCALE_F + bias_s[idx - 8];
            float o3 = acc[tm][t8][3] * SCALE_F + bias_s[idx - 7];
            *(float2*)(P0b + (size_t)(q0 + q) * 1024 + k0 + k) = make_float2(o0, o1);
            *(float2*)(P0b + (size_t)(q0 + q + 8) * 1024 + k0 + k) = make_float2(o2, o3);
        }
    }
}

// ---------------------------------------------------------------------------
// Flash attention, deferred-PV pipelined + P0 register hoist.
// ---------------------------------------------------------------------------
#define KROW2 144
#define KB2 9216
#define P0ROW 272
#define STG (3 * KB2 + 64 * P0ROW)   // 45056
#define FL_SMEM (2 * STG)            // 90112

__device__ __forceinline__ void fl_prefetch_KP(uint32_t sb, int b, int h, int hc,
                                               int q0, int k0, int s, int tid) {
    const uint32_t kb = sb + s * STG;
    const size_t rb = ((size_t)b * S_LEN + k0) * 3072;
#pragma unroll
    for (int it = 0; it < 4; it++) {
        int e = tid + (it << 7);
        int k = e >> 3, c = e & 7;
        size_t so = rb + (size_t)k * 3072 + hc + c * 8;
        uint32_t o = k * KROW2 + c * 16;
        cp_async16(kb + o, g_th + so);
        cp_async16(kb + KB2 + o, g_tl + so);
    }
    const float* p0src = g_P0 + ((size_t)h << 20) + (size_t)q0 * 1024 + k0;
#pragma unroll
    for (int it = 0; it < 8; it++) {
        int e = tid + (it << 7);
        int r = e >> 4, c = e & 15;
        cp_async16(kb + 3 * KB2 + r * P0ROW + c * 16, p0src + (size_t)r * 1024 + c * 4);
    }
}

__device__ __forceinline__ void fl_prefetch_V(uint32_t sb, int b, int hc,
                                              int k0, int s, int tid) {
    const uint32_t vb = sb + s * STG + 2 * KB2;
    const size_t rb = ((size_t)b * S_LEN + k0) * 3072;
#pragma unroll
    for (int it = 0; it < 4; it++) {
        int e = tid + (it << 7);
        int k = e >> 3, c = e & 7;
        size_t sv = rb + (size_t)k * 3072 + 2048 + hc + c * 8;
        cp_async16(vb + k * KROW2 + c * 16, g_th + sv);
    }
}

__global__ void __launch_bounds__(128, 2) flash_kernel(float* __restrict__ out) {
    extern __shared__ char sm[];
    const uint32_t sb = smem_u32(sm);
    const int tid = threadIdx.x, lane = tid & 31, wid = tid >> 5;
    const int lj = lane >> 3, lr = lane & 7;
    const int b = blockIdx.z, h = blockIdx.y, q0 = blockIdx.x * 64;
    const int hc = h * 64;
    const int m0w = wid * 16;

    {
        const size_t rb = ((size_t)b * S_LEN + q0) * 3072;
#pragma unroll
        for (int it = 0; it < 4; it++) {
            int e = tid + (it << 7);
            int q = e >> 3, c = e & 7;
            size_t so = rb + (size_t)q * 3072 + 1024 + hc + c * 8;
            cp_async16(sb + q * KROW2 + c * 16, g_th + so);
            cp_async16(sb + STG + q * KROW2 + c * 16, g_tl + so);
        }
        CP_COMMIT();
        CP_WAIT(0);
        __syncthreads();
    }
    uint32_t qh[4][4], qlo[4][4];
#pragma unroll
    for (int dk = 0; dk < 4; dk++) {
        uint32_t qa = sb + (m0w + (lj & 1) * 8 + lr) * KROW2 + (dk * 16 + (lj >> 1) * 8) * 2;
        ldm_x4(qh[dk], qa);
        ldm_x4(qlo[dk], qa + STG);
    }
    __syncthreads();

    fl_prefetch_KP(sb, b, h, hc, q0, 0, 0, tid);
    CP_COMMIT();
    fl_prefetch_V(sb, b, hc, 0, 0, tid);
    CP_COMMIT();

    float O[8][4];
#pragma unroll
    for (int i = 0; i < 8; i++)
#pragma unroll
        for (int j = 0; j < 4; j++) O[i][j] = 0.f;
    float m0 = -INFINITY, m1 = -INFINITY, l0 = 0.f, l1 = 0.f;
    uint32_t ph0[8], ph1[8];   // P(kt-1), consumed one iteration late

    const float LOG2E = 1.4426950408889634f;
    const int NT = S_LEN / 64;
    const int qr = m0w + (lane >> 2);

    for (int kt = 0; kt < NT; kt++) {
        const int s = kt & 1;

        CP_WAIT(1);
        __syncthreads();

        if (kt + 1 < NT) {
            fl_prefetch_KP(sb, b, h, hc, q0, (kt + 1) * 64, s ^ 1, tid);
            CP_COMMIT();
        }

        const uint32_t khb = sb + s * STG;
        const char* p0s = sm + s * STG + 3 * KB2;

        // ---- P0 register hoist: issue LDS before QK MMAs (latency hidden) ----
        float2 pb0[8], pb1[8];
#pragma unroll
        for (int tt = 0; tt < 8; tt++) {
            int kl = 8 * tt + 2 * (lane & 3);
            pb0[tt] = *(const float2*)(p0s + qr * P0ROW + kl * 4);
            pb1[tt] = *(const float2*)(p0s + (qr + 8) * P0ROW + kl * 4);
        }

        // ---- S = Q K^T (hi/lo 3-pass, de=64) ----
        float Sa[8][4];
#pragma unroll
        for (int i = 0; i < 8; i++)
#pragma unroll
            for (int j = 0; j < 4; j++) Sa[i][j] = 0.f;

#pragma unroll
        for (int dk = 0; dk < 4; dk++) {
#pragma unroll
            for (int ng = 0; ng < 4; ng++) {
                uint32_t bh[4], bl[4];
                uint32_t ka = khb + (ng * 16 + (lj >> 1) * 8 + lr) * KROW2 + (dk * 16 + (lj & 1) * 8) * 2;
                ldm_x4(bh, ka);
                ldm_x4(bl, ka + KB2);
                uint32_t b0[2] = {bh[0], bh[1]}, c0[2] = {bl[0], bl[1]};
                mma_f16(Sa[2 * ng], qh[dk], b0);
                mma_f16(Sa[2 * ng], qh[dk], c0);
                mma_f16(Sa[2 * ng], qlo[dk], b0);
                uint32_t b1[2] = {bh[2], bh[3]}, c1[2] = {bl[2], bl[3]};
                mma_f16(Sa[2 * ng + 1], qh[dk], b1);
                mma_f16(Sa[2 * ng + 1], qh[dk], c1);
                mma_f16(Sa[2 * ng + 1], qlo[dk], b1);
            }
        }

        // ---- add P0 (registers), row max ----
        float mx0 = -INFINITY, mx1 = -INFINITY;
#pragma unroll
        for (int tt = 0; tt < 8; tt++) {
            float s0 = Sa[tt][0] * SCALE_F + pb0[tt].x;
            float s1 = Sa[tt][1] * SCALE_F + pb0[tt].y;
            float s2 = Sa[tt][2] * SCALE_F + pb1[tt].x;
            float s3 = Sa[tt][3] * SCALE_F + pb1[tt].y;
            Sa[tt][0] = s0; Sa[tt][1] = s1; Sa[tt][2] = s2; Sa[tt][3] = s3;
            mx0 = fmaxf(mx0, fmaxf(s0, s1));
            mx1 = fmaxf(mx1, fmaxf(s2, s3));
        }
        mx0 = fmaxf(mx0, __shfl_xor_sync(0xffffffffu, mx0, 1));
        mx0 = fmaxf(mx0, __shfl_xor_sync(0xffffffffu, mx0, 2));
        mx1 = fmaxf(mx1, __shfl_xor_sync(0xffffffffu, mx1, 1));
        mx1 = fmaxf(mx1, __shfl_xor_sync(0xffffffffu, mx1, 2));
        float mn0 = fmaxf(m0, mx0), mn1 = fmaxf(m1, mx1);
        float a0 = exp2f((m0 - mn0) * LOG2E), a1 = exp2f((m1 - mn1) * LOG2E);
        m0 = mn0; m1 = mn1;

        // ---- deferred PV(kt-1): tensor work overlapping softmax ----
        if (kt > 0) {
            const uint32_t vprev = sb + (s ^ 1) * STG + 2 * KB2;
#pragma unroll
            for (int ck = 0; ck < 4; ck++) {
                uint32_t Ah[4] = {ph0[2 * ck], ph1[2 * ck], ph0[2 * ck + 1], ph1[2 * ck + 1]};
#pragma unroll
                for (int dg = 0; dg < 4; dg++) {
                    uint32_t vh[4];
                    uint32_t va = vprev + (ck * 16 + (lj & 1) * 8 + lr) * KROW2 + (dg * 16 + (lj >> 1) * 8) * 2;
                    ldm_x4t(vh, va);
                    uint32_t v0[2] = {vh[0], vh[1]};
                    mma_f16(O[2 * dg], Ah, v0);
                    uint32_t v1[2] = {vh[2], vh[3]};
                    mma_f16(O[2 * dg + 1], Ah, v1);
                }
            }
        }

        // ---- exp, pack new P, row sums (interleaves with PV drain) ----
        float r0 = 0.f, r1 = 0.f;
#pragma unroll
        for (int tt = 0; tt < 8; tt++) {
            float p0 = exp2f((Sa[tt][0] - m0) * LOG2E);
            float p1 = exp2f((Sa[tt][1] - m0) * LOG2E);
            float p2 = exp2f((Sa[tt][2] - m1) * LOG2E);
            float p3 = exp2f((Sa[tt][3] - m1) * LOG2E);
            r0 += p0 + p1; r1 += p2 + p3;
            ph0[tt] = h2u(__floats2half2_rn(p0, p1));
            ph1[tt] = h2u(__floats2half2_rn(p2, p3));
        }
        r0 += __shfl_xor_sync(0xffffffffu, r0, 1);
        r0 += __shfl_xor_sync(0xffffffffu, r0, 2);
        r1 += __shfl_xor_sync(0xffffffffu, r1, 1);
        r1 += __shfl_xor_sync(0xffffffffu, r1, 2);
        l0 = l0 * a0 + r0;
        l1 = l1 * a1 + r1;

#pragma unroll
        for (int dt = 0; dt < 8; dt++) {
            O[dt][0] *= a0; O[dt][1] *= a0; O[dt][2] *= a1; O[dt][3] *= a1;
        }

        __syncthreads();
        if (kt + 1 < NT) {
            fl_prefetch_V(sb, b, hc, (kt + 1) * 64, s ^ 1, tid);
            CP_COMMIT();
        }
    }

    // ---- final PV(NT-1) ----
    CP_WAIT(0);
    __syncthreads();
    {
        const uint32_t vlast = sb + ((NT - 1) & 1) * STG + 2 * KB2;
#pragma unroll
        for (int ck = 0; ck < 4; ck++) {
            uint32_t Ah[4] = {ph0[2 * ck], ph1[2 * ck], ph0[2 * ck + 1], ph1[2 * ck + 1]};
#pragma unroll
            for (int dg = 0; dg < 4; dg++) {
                uint32_t vh[4];
                uint32_t va = vlast + (ck * 16 + (lj & 1) * 8 + lr) * KROW2 + (dg * 16 + (lj >> 1) * 8) * 2;
                ldm_x4t(vh, va);
                uint32_t v0[2] = {vh[0], vh[1]};
                mma_f16(O[2 * dg], Ah, v0);
                uint32_t v1[2] = {vh[2], vh[3]};
                mma_f16(O[2 * dg + 1], Ah, v1);
            }
        }
    }

    float inv0 = 1.f / l0, inv1 = 1.f / l1;
    size_t row = (size_t)b * S_LEN + q0 + m0w + (lane >> 2);
#pragma unroll
    for (int dt = 0; dt < 8; dt++) {
        int n = hc + dt * 8 + 2 * (lane & 3);
        *(float2*)(out + row * D_MOD + n) = make_float2(O[dt][0] * inv0, O[dt][1] * inv0);
        *(float2*)(out + (row + 8) * D_MOD + n) = make_float2(O[dt][2] * inv1, O[dt][3] * inv1);
    }
}

// ---------------------------------------------------------------------------
// Launch (single stream — block-range fusion)
// ---------------------------------------------------------------------------
extern "C" void kernel_launch(void* const* d_in, const int* in_sizes, int n_in,
                              void* d_out, int out_size) {
    const float* x          = (const float*)d_in[0];
    const float* gamma      = (const float*)d_in[1];
    const float* beta       = (const float*)d_in[2];
    const float* w_pos      = (const float*)d_in[3];
    const float* w_tok      = (const float*)d_in[4];
    const float* bias_table = (const float*)d_in[5];
    float* out = (float*)d_out;

    cudaFuncSetAttribute(gemm_merged, cudaFuncAttributeMaxDynamicSharedMemorySize, GEMM_SMEM);
    cudaFuncSetAttribute(posattn_kernel, cudaFuncAttributeMaxDynamicSharedMemorySize, PA_SMEM);
    cudaFuncSetAttribute(flash_kernel, cudaFuncAttributeMaxDynamicSharedMemorySize, FL_SMEM);

    // fused elementwise: pe (sincosf pairs) + w_pos split + w_tok split + layernorm
    prep_kernel<<<10240, 256>>>(w_pos, w_tok, x, gamma, beta);
    // merged GEMMs: tok (768 blocks) + pos (128 blocks), occ 2
    gemm_merged<<<896, 256, GEMM_SMEM>>>();
    // P0 = pos_attn*SCALE + bias (batch-independent)
    posattn_kernel<<<dim3(8, 8, 16), 256, PA_SMEM>>>(bias_table);
    // flash attention (deferred-PV + P0 register hoist, occ 2)
    flash_kernel<<<dim3(S_LEN / 64, N_H, B_SZ), 128, FL_SMEM>>>(out);
}